// round 4
// baseline (speedup 1.0000x reference)
#include <cuda_runtime.h>

// Problem constants
#define DM    100
#define NSDK  2048
#define ROWS  1024        // SZ_B * L
#define DI_   400
#define KSPLIT 8
#define PART_STRIDE (ROWS * DM)

// Scratch (device globals — no allocation)
__device__ float g_att[ROWS * NSDK];          // attention output [1024][2048]
__device__ float g_part[KSPLIT * PART_STRIDE];// fc split-K partials
__device__ float g_ln1[ROWS * DM];            // LN1 output
__device__ float g_h[ROWS * DI_];             // MLP hidden [1024][400]

// ---------------------------------------------------------------------------
// tf32 helpers
// ---------------------------------------------------------------------------
__device__ __forceinline__ unsigned f2tf(float v) {
    unsigned r;
    asm("cvt.rna.tf32.f32 %0, %1;" : "=r"(r) : "f"(v));
    return r;
}

__device__ __forceinline__ void mma_tf32(float c[4],
                                         unsigned a0, unsigned a1, unsigned a2, unsigned a3,
                                         unsigned b0, unsigned b1) {
    asm("mma.sync.aligned.m16n8k8.row.col.f32.tf32.tf32.f32 "
        "{%0,%1,%2,%3},{%4,%5,%6,%7},{%8,%9},{%0,%1,%2,%3};"
        : "+f"(c[0]), "+f"(c[1]), "+f"(c[2]), "+f"(c[3])
        : "r"(a0), "r"(a1), "r"(a2), "r"(a3), "r"(b0), "r"(b1));
}

// ---------------------------------------------------------------------------
// K1: FUSED QKV projection + attention.
// Block: 384 threads (12 warps), tile = 64 rows (32 batches) x 1 ns (32 cols),
// all 3 projections. Warp w: projection (w>>2), m-slice ((w&3)*16).
// After GEMM, Q/K/V staged in smem (union with GEMM tiles), then the
// 34-way softmax (no max-subtract; diag via exp(-1e30)=0) -> g_att.
// grid (64 ns, 16 rowtiles)
// ---------------------------------------------------------------------------
__global__ __launch_bounds__(384) void qkv_attn(
        const float* __restrict__ edges,
        const float* __restrict__ wq, const float* __restrict__ bq,
        const float* __restrict__ wk, const float* __restrict__ bk,
        const float* __restrict__ wv, const float* __restrict__ bv,
        const float* __restrict__ qcw, const float* __restrict__ qcb,
        const float* __restrict__ kcw, const float* __restrict__ kcb,
        const float* __restrict__ vcw, const float* __restrict__ vcb)
{
    __shared__ float buf[6336];     // union: GEMM 5632 words | ATT 6336 words
    unsigned* As = (unsigned*)buf;              // [32][72]  (k-major, pitch 72)
    unsigned* Bs = (unsigned*)buf + 2304;       // [32][104] (3 proj at +0/+34/+68)
    float* sq = buf;                            // [64][33]
    float* sk = buf + 2112;
    float* sv = buf + 4224;

    const int t    = threadIdx.x;
    const int lane = t & 31;
    const int wid  = t >> 5;
    const int tig  = lane & 3;
    const int gid  = lane >> 2;

    const int ns   = blockIdx.x;
    const int row0 = blockIdx.y * 64;

    const int pw = wid >> 2;          // projection handled by this warp
    const int m0 = (wid & 3) * 16;    // m-slice

    float acc[4][4] = {};

    for (int kc = 0; kc < 4; kc++) {
        const int kb = kc * 32;
        __syncthreads();
        // A: edges tile [64 rows][32 k]
        #pragma unroll
        for (int idx = t; idx < 2048; idx += 384) {
            int kk = idx & 31, m = idx >> 5;
            int k  = kb + kk;
            As[kk * 72 + m] = f2tf(k < DM ? edges[(row0 + m) * DM + k] : 0.0f);
        }
        // B: 3 weight slices [32 cols][32 k] each
        #pragma unroll
        for (int idx = t; idx < 3072; idx += 384) {
            int kk = idx & 31;
            int rest = idx >> 5;          // 0..95
            int p = rest >> 5;
            int n = rest & 31;
            int k = kb + kk;
            const float* W = (p == 0) ? wq : (p == 1) ? wk : wv;
            Bs[kk * 104 + p * 34 + n] =
                f2tf(k < DM ? W[(ns * 32 + n) * DM + k] : 0.0f);
        }
        __syncthreads();

        #pragma unroll
        for (int ks = 0; ks < 4; ks++) {
            const int k0 = ks * 8;
            unsigned a0 = As[(k0 + tig) * 72 + m0 + gid];
            unsigned a1 = As[(k0 + tig) * 72 + m0 + gid + 8];
            unsigned a2 = As[(k0 + tig + 4) * 72 + m0 + gid];
            unsigned a3 = As[(k0 + tig + 4) * 72 + m0 + gid + 8];
            unsigned b[4][2];
            #pragma unroll
            for (int j = 0; j < 4; j++) {
                int nb = pw * 34 + j * 8;
                b[j][0] = Bs[(k0 + tig) * 104 + nb + gid];
                b[j][1] = Bs[(k0 + tig + 4) * 104 + nb + gid];
            }
            #pragma unroll
            for (int j = 0; j < 4; j++)
                mma_tf32(acc[j], a0, a1, a2, a3, b[j][0], b[j][1]);
        }
    }

    __syncthreads();   // all mma smem reads done before union overwrite

    // epilogue: affine + bias, stage into sq/sk/sv
    {
        const float scale = (pw == 0) ? *qcw : (pw == 1) ? *kcw : *vcw;
        const float shift = (pw == 0) ? *qcb : (pw == 1) ? *kcb : *vcb;
        const float* bias = (pw == 0) ? bq : (pw == 1) ? bk : bv;
        float* sX = (pw == 0) ? sq : (pw == 1) ? sk : sv;

        #pragma unroll
        for (int j = 0; j < 4; j++) {
            const int col = j * 8 + 2 * tig;
            const float b0v = bias[ns * 32 + col];
            const float b1v = bias[ns * 32 + col + 1];
            const int r0 = m0 + gid;
            sX[r0 * 33 + col]           = fmaf(scale, acc[j][0] + b0v, shift);
            sX[r0 * 33 + col + 1]       = fmaf(scale, acc[j][1] + b1v, shift);
            sX[(r0 + 8) * 33 + col]     = fmaf(scale, acc[j][2] + b0v, shift);
            sX[(r0 + 8) * 33 + col + 1] = fmaf(scale, acc[j][3] + b1v, shift);
        }
    }
    __syncthreads();

    // attention: 2048 items = 32 batches x 64 (h,w) flats
    for (int idx = t; idx < 2048; idx += 384) {
        const int bloc = idx >> 6;
        const int lt   = idx & 63;     // flat = h*2+w = l*32+dk
        const int rb   = 2 * bloc;
        const int w    = lt & 1;
        const int h    = lt >> 1;

        const float q = sq[(rb + (lt >> 5)) * 33 + (lt & 31)];

        float e[32];
        #pragma unroll
        for (int g = 0; g < 32; g++) {
            int f = 2 * g + w;
            e[g] = (g == h) ? -1e30f
                            : q * sk[(rb + (f >> 5)) * 33 + (f & 31)];
        }
        const int f0 = lt & ~1;        // 2h
        const float ew0 = q * sk[(rb + (f0 >> 5)) * 33 + (f0 & 31)];
        const float ew1 = q * sk[(rb + ((f0 + 1) >> 5)) * 33 + ((f0 + 1) & 31)];

        float p0 = __expf(ew0);
        float p1 = __expf(ew1);
        float Z   = p0 + p1;
        float acc2 = p0 * sv[(rb + (f0 >> 5)) * 33 + (f0 & 31)]
                   + p1 * sv[(rb + ((f0 + 1) >> 5)) * 33 + ((f0 + 1) & 31)];
        #pragma unroll
        for (int g = 0; g < 32; g++) {
            int f = 2 * g + w;
            float pz = __expf(e[g]);
            Z   += pz;
            acc2 = fmaf(pz, sv[(rb + (f >> 5)) * 33 + (f & 31)], acc2);
        }
        const float o = acc2 / Z;
        const int grow = row0 + rb + (lt >> 5);
        g_att[grow * NSDK + ns * 32 + (lt & 31)] = o;
    }
}

// ---------------------------------------------------------------------------
// K2: fc GEMM split-K partials (tf32). Block tile 64(M) x 112(N), 128 thr.
// grid (16 mtiles, 8 ksplits); each ksplit covers K=256 (8 chunks).
// ---------------------------------------------------------------------------
__global__ __launch_bounds__(128) void fc_tc(const float* __restrict__ fcw)
{
    __shared__ unsigned As[32 * 72];
    __shared__ unsigned Bs[32 * 120];

    const int t    = threadIdx.x;
    const int lane = t & 31;
    const int wid  = t >> 5;
    const int tig  = lane & 3;
    const int gid  = lane >> 2;

    const int row0 = blockIdx.x * 64;
    const int ks   = blockIdx.y;

    const int wm0 = (wid >> 1) * 32;
    const int wn0 = (wid & 1) * 56;

    float acc[2][7][4] = {};

    for (int kc = 0; kc < 8; kc++) {
        const int kb = ks * 256 + kc * 32;
        __syncthreads();
        #pragma unroll
        for (int idx = t; idx < 2048; idx += 128) {
            int kk = idx & 31, m = idx >> 5;
            As[kk * 72 + m] = f2tf(g_att[(row0 + m) * NSDK + kb + kk]);
        }
        #pragma unroll
        for (int idx = t; idx < 3584; idx += 128) {
            int kk = idx & 31, n = idx >> 5;
            Bs[kk * 120 + n] = f2tf(n < DM ? fcw[n * NSDK + kb + kk] : 0.0f);
        }
        __syncthreads();

        #pragma unroll
        for (int kss = 0; kss < 4; kss++) {
            const int k0 = kss * 8;
            unsigned a[2][4];
            #pragma unroll
            for (int i = 0; i < 2; i++) {
                int mb = wm0 + i * 16;
                a[i][0] = As[(k0 + tig) * 72 + mb + gid];
                a[i][1] = As[(k0 + tig) * 72 + mb + gid + 8];
                a[i][2] = As[(k0 + tig + 4) * 72 + mb + gid];
                a[i][3] = As[(k0 + tig + 4) * 72 + mb + gid + 8];
            }
            unsigned b[7][2];
            #pragma unroll
            for (int j = 0; j < 7; j++) {
                int nb = wn0 + j * 8;
                b[j][0] = Bs[(k0 + tig) * 120 + nb + gid];
                b[j][1] = Bs[(k0 + tig + 4) * 120 + nb + gid];
            }
            #pragma unroll
            for (int i = 0; i < 2; i++)
                #pragma unroll
                for (int j = 0; j < 7; j++)
                    mma_tf32(acc[i][j], a[i][0], a[i][1], a[i][2], a[i][3],
                             b[j][0], b[j][1]);
        }
    }

    #pragma unroll
    for (int i = 0; i < 2; i++) {
        #pragma unroll
        for (int j = 0; j < 7; j++) {
            const int col = wn0 + j * 8 + 2 * tig;
            if (col < DM) {
                int r0 = row0 + wm0 + i * 16 + gid;
                *(float2*)&g_part[ks * PART_STRIDE + r0 * DM + col] =
                    make_float2(acc[i][j][0], acc[i][j][1]);
                *(float2*)&g_part[ks * PART_STRIDE + (r0 + 8) * DM + col] =
                    make_float2(acc[i][j][2], acc[i][j][3]);
            }
        }
    }
}

// ---------------------------------------------------------------------------
// K3: reduce partials + bias + residual + LayerNorm1. Warp per row.
// ---------------------------------------------------------------------------
__global__ void ln1_kernel(const float* __restrict__ edges,
                           const float* __restrict__ fcb,
                           const float* __restrict__ g1,
                           const float* __restrict__ b1)
{
    const int wid  = threadIdx.x >> 5;
    const int lane = threadIdx.x & 31;
    const int row  = blockIdx.x * 8 + wid;

    float x[4];
    #pragma unroll
    for (int i = 0; i < 4; i++) {
        int c = lane + i * 32;
        float v = 0.0f;
        if (c < DM) {
            v = fcb[c] + edges[row * DM + c];
            #pragma unroll
            for (int s = 0; s < KSPLIT; s++)
                v += g_part[s * PART_STRIDE + row * DM + c];
        }
        x[i] = v;
    }

    float s = x[0] + x[1] + x[2] + x[3];
    #pragma unroll
    for (int off = 16; off > 0; off >>= 1) s += __shfl_xor_sync(0xffffffffu, s, off);
    const float mean = s * (1.0f / DM);

    float v2 = 0.0f;
    #pragma unroll
    for (int i = 0; i < 4; i++) {
        int c = lane + i * 32;
        if (c < DM) {
            float d = x[i] - mean;
            v2 = fmaf(d, d, v2);
        }
    }
    #pragma unroll
    for (int off = 16; off > 0; off >>= 1) v2 += __shfl_xor_sync(0xffffffffu, v2, off);
    const float inv = rsqrtf(v2 * (1.0f / DM) + 1e-5f);

    #pragma unroll
    for (int i = 0; i < 4; i++) {
        int c = lane + i * 32;
        if (c < DM)
            g_ln1[row * DM + c] = (x[i] - mean) * inv * g1[c] + b1[c];
    }
}

// ---------------------------------------------------------------------------
// K4: MLP layer 1 (tf32): h = relu(ln1 @ w1^T + b1). Block 32(M) x 128(N).
// grid (4, 32), 128 threads.
// ---------------------------------------------------------------------------
__global__ __launch_bounds__(128) void mlp_l1_tc(const float* __restrict__ w1,
                                                 const float* __restrict__ b1)
{
    __shared__ unsigned As[32 * 40];
    __shared__ unsigned Bs[32 * 136];

    const int t    = threadIdx.x;
    const int lane = t & 31;
    const int wid  = t >> 5;
    const int tig  = lane & 3;
    const int gid  = lane >> 2;

    const int col0 = blockIdx.x * 128;
    const int row0 = blockIdx.y * 32;

    const int wm0 = (wid >> 1) * 16;
    const int wn0 = (wid & 1) * 64;

    float acc[8][4] = {};

    for (int kc = 0; kc < 4; kc++) {
        const int kb = kc * 32;
        __syncthreads();
        #pragma unroll
        for (int idx = t; idx < 1024; idx += 128) {
            int kk = idx & 31, m = idx >> 5;
            int k  = kb + kk;
            As[kk * 40 + m] = f2tf(k < DM ? g_ln1[(row0 + m) * DM + k] : 0.0f);
        }
        #pragma unroll
        for (int idx = t; idx < 4096; idx += 128) {
            int kk = idx & 31, n = idx >> 5;
            int k  = kb + kk;
            int gc = col0 + n;
            Bs[kk * 136 + n] = f2tf((k < DM && gc < DI_) ? w1[gc * DM + k] : 0.0f);
        }
        __syncthreads();

        #pragma unroll
        for (int ks = 0; ks < 4; ks++) {
            const int k0 = ks * 8;
            unsigned a0 = As[(k0 + tig) * 40 + wm0 + gid];
            unsigned a1 = As[(k0 + tig) * 40 + wm0 + gid + 8];
            unsigned a2 = As[(k0 + tig + 4) * 40 + wm0 + gid];
            unsigned a3 = As[(k0 + tig + 4) * 40 + wm0 + gid + 8];
            unsigned b[8][2];
            #pragma unroll
            for (int j = 0; j < 8; j++) {
                int nb = wn0 + j * 8;
                b[j][0] = Bs[(k0 + tig) * 136 + nb + gid];
                b[j][1] = Bs[(k0 + tig + 4) * 136 + nb + gid];
            }
            #pragma unroll
            for (int j = 0; j < 8; j++)
                mma_tf32(acc[j], a0, a1, a2, a3, b[j][0], b[j][1]);
        }
    }

    #pragma unroll
    for (int j = 0; j < 8; j++) {
        const int colg = col0 + wn0 + j * 8 + 2 * tig;
        if (colg < DI_) {
            const float b0v = b1[colg];
            const float b1v = b1[colg + 1];
            int r0 = row0 + wm0 + gid;
            float2 v0, v1;
            v0.x = fmaxf(acc[j][0] + b0v, 0.0f);
            v0.y = fmaxf(acc[j][1] + b1v, 0.0f);
            v1.x = fmaxf(acc[j][2] + b0v, 0.0f);
            v1.y = fmaxf(acc[j][3] + b1v, 0.0f);
            *(float2*)&g_h[r0 * DI_ + colg]       = v0;
            *(float2*)&g_h[(r0 + 8) * DI_ + colg] = v1;
        }
    }
}

// ---------------------------------------------------------------------------
// K5: MLP layer 2 (tf32) + bias + residual + LayerNorm2 -> d_out.
// Block tile 16(M) x 112(N), in-block 2-way split-K (each half K=224 padded).
// 128 threads: warp = (k-half, n-half). grid 64.
// ---------------------------------------------------------------------------
__global__ __launch_bounds__(128) void mlp_l2_tc(const float* __restrict__ w2,
                                                 const float* __restrict__ b2,
                                                 const float* __restrict__ g2,
                                                 const float* __restrict__ bb2,
                                                 float* __restrict__ outp)
{
    __shared__ float buf[9216];          // union: As/Bs (9216 w) | ys (3616 w)
    unsigned* As = (unsigned*)buf;       // [2][32*24]
    unsigned* Bs = (unsigned*)buf + 1536;// [2][32*120]
    float* ys = buf;                     // [2][16][113]

    const int t    = threadIdx.x;
    const int lane = t & 31;
    const int wid  = t >> 5;
    const int tig  = lane & 3;
    const int gid  = lane >> 2;

    const int row0 = blockIdx.x * 16;
    const int kh   = wid >> 1;           // K half
    const int nh   = wid & 1;            // N half
    const int wn0  = nh * 56;

    float acc[7][4] = {};

    for (int kc = 0; kc < 7; kc++) {
        const int kb = kc * 32;
        __syncthreads();
        #pragma unroll
        for (int idx = t; idx < 1024; idx += 128) {
            int half = idx >> 9;
            int rem  = idx & 511;
            int kk = rem & 31, m = rem >> 5;
            int k  = half * 224 + kb + kk;
            As[half * 768 + kk * 24 + m] =
                f2tf(k < DI_ ? g_h[(row0 + m) * DI_ + k] : 0.0f);
        }
        #pragma unroll
        for (int idx = t; idx < 7168; idx += 128) {
            int half = idx >= 3584;
            int rem  = idx - half * 3584;
            int kk = rem & 31, n = rem >> 5;
            int k  = half * 224 + kb + kk;
            Bs[half * 3840 + kk * 120 + n] =
                f2tf((n < DM && k < DI_) ? w2[n * DI_ + k] : 0.0f);
        }
        __syncthreads();

        const unsigned* Ah = As + kh * 768;
        const unsigned* Bh = Bs + kh * 3840;
        #pragma unroll
        for (int kss = 0; kss < 4; kss++) {
            const int k0 = kss * 8;
            unsigned a0 = Ah[(k0 + tig) * 24 + gid];
            unsigned a1 = Ah[(k0 + tig) * 24 + gid + 8];
            unsigned a2 = Ah[(k0 + tig + 4) * 24 + gid];
            unsigned a3 = Ah[(k0 + tig + 4) * 24 + gid + 8];
            unsigned b[7][2];
            #pragma unroll
            for (int j = 0; j < 7; j++) {
                int nb = wn0 + j * 8;
                b[j][0] = Bh[(k0 + tig) * 120 + nb + gid];
                b[j][1] = Bh[(k0 + tig + 4) * 120 + nb + gid];
            }
            #pragma unroll
            for (int j = 0; j < 7; j++)
                mma_tf32(acc[j], a0, a1, a2, a3, b[j][0], b[j][1]);
        }
    }

    __syncthreads();    // done reading As/Bs; union -> ys
    #pragma unroll
    for (int j = 0; j < 7; j++) {
        const int col = wn0 + j * 8 + 2 * tig;
        ys[kh * 1808 + gid * 113 + col]           = acc[j][0];
        ys[kh * 1808 + gid * 113 + col + 1]       = acc[j][1];
        ys[kh * 1808 + (gid + 8) * 113 + col]     = acc[j][2];
        ys[kh * 1808 + (gid + 8) * 113 + col + 1] = acc[j][3];
    }
    __syncthreads();

    // LN2: quad per row (threads 0..63 cover 16 rows)
    if (t < 64) {
        const int r    = t >> 2;
        const int s4   = t & 3;
        const int grow = row0 + r;

        float vals[25];
        float sum = 0.0f;
        #pragma unroll
        for (int j = 0; j < 25; j++) {
            int c = s4 + 4 * j;
            float v = ys[r * 113 + c] + ys[1808 + r * 113 + c]
                    + b2[c] + g_ln1[grow * DM + c];
            vals[j] = v;
            sum += v;
        }
        sum += __shfl_xor_sync(0xffffffffu, sum, 1);
        sum += __shfl_xor_sync(0xffffffffu, sum, 2);
        const float mean = sum * (1.0f / DM);

        float v2 = 0.0f;
        #pragma unroll
        for (int j = 0; j < 25; j++) {
            float d = vals[j] - mean;
            v2 = fmaf(d, d, v2);
        }
        v2 += __shfl_xor_sync(0xffffffffu, v2, 1);
        v2 += __shfl_xor_sync(0xffffffffu, v2, 2);
        const float inv = rsqrtf(v2 * (1.0f / DM) + 1e-5f);

        #pragma unroll
        for (int j = 0; j < 25; j++) {
            int c = s4 + 4 * j;
            outp[grow * DM + c] = (vals[j] - mean) * inv * g2[c] + bb2[c];
        }
    }
}

// ---------------------------------------------------------------------------
extern "C" void kernel_launch(void* const* d_in, const int* in_sizes, int n_in,
                              void* d_out, int out_size)
{
    (void)in_sizes; (void)n_in; (void)out_size;
    const float* edges = (const float*)d_in[0];
    const float* wq    = (const float*)d_in[1];
    const float* bq    = (const float*)d_in[2];
    const float* wk    = (const float*)d_in[3];
    const float* bk    = (const float*)d_in[4];
    const float* wv    = (const float*)d_in[5];
    const float* bv    = (const float*)d_in[6];
    const float* qcw   = (const float*)d_in[7];
    const float* qcb   = (const float*)d_in[8];
    const float* kcw   = (const float*)d_in[9];
    const float* kcb   = (const float*)d_in[10];
    const float* vcw   = (const float*)d_in[11];
    const float* vcb   = (const float*)d_in[12];
    const float* fcw   = (const float*)d_in[13];
    const float* fcb   = (const float*)d_in[14];
    const float* ln1g  = (const float*)d_in[15];
    const float* ln1b  = (const float*)d_in[16];
    const float* w1w   = (const float*)d_in[17];
    const float* w1b   = (const float*)d_in[18];
    const float* w2w   = (const float*)d_in[19];
    const float* w2b   = (const float*)d_in[20];
    const float* ln2g  = (const float*)d_in[21];
    const float* ln2b  = (const float*)d_in[22];

    qkv_attn<<<dim3(64, 16), 384>>>(edges, wq, bq, wk, bk, wv, bv,
                                    qcw, qcb, kcw, kcb, vcw, vcb);
    fc_tc<<<dim3(16, KSPLIT), 128>>>(fcw);
    ln1_kernel<<<ROWS / 8, 256>>>(edges, fcb, ln1g, ln1b);
    mlp_l1_tc<<<dim3(4, 32), 128>>>(w1w, w1b);
    mlp_l2_tc<<<64, 128>>>(w2w, w2b, ln2g, ln2b, (float*)d_out);
}

// round 5
// speedup vs baseline: 1.5621x; 1.5621x over previous
#include <cuda_runtime.h>

// Problem constants
#define DM    100
#define NSDK  2048
#define ROWS  1024        // SZ_B * L
#define DI_   400
#define KSPLIT 8
#define PART_STRIDE (ROWS * DM)

// Scratch (device globals — no allocation)
__device__ float g_att[ROWS * NSDK];          // attention output [1024][2048]
__device__ float g_part[KSPLIT * PART_STRIDE];// fc split-K partials
__device__ float g_ln1[ROWS * DM];            // LN1 output
__device__ float g_h[ROWS * DI_];             // MLP hidden [1024][400]

// ---------------------------------------------------------------------------
// helpers
// ---------------------------------------------------------------------------
__device__ __forceinline__ unsigned f2tf(float v) {
    unsigned r;
    asm("cvt.rna.tf32.f32 %0, %1;" : "=r"(r) : "f"(v));
    return r;
}

__device__ __forceinline__ void mma_tf32(float c[4],
                                         unsigned a0, unsigned a1, unsigned a2, unsigned a3,
                                         unsigned b0, unsigned b1) {
    asm("mma.sync.aligned.m16n8k8.row.col.f32.tf32.tf32.f32 "
        "{%0,%1,%2,%3},{%4,%5,%6,%7},{%8,%9},{%0,%1,%2,%3};"
        : "+f"(c[0]), "+f"(c[1]), "+f"(c[2]), "+f"(c[3])
        : "r"(a0), "r"(a1), "r"(a2), "r"(a3), "r"(b0), "r"(b1));
}

__device__ __forceinline__ unsigned sa(const void* p) {
    return (unsigned)__cvta_generic_to_shared(p);
}
__device__ __forceinline__ void cp16(unsigned d, const void* s) {
    asm volatile("cp.async.ca.shared.global [%0], [%1], 16;" :: "r"(d), "l"(s));
}
__device__ __forceinline__ void cp16z(unsigned d, const void* s, int srcbytes) {
    asm volatile("cp.async.ca.shared.global [%0], [%1], 16, %2;"
                 :: "r"(d), "l"(s), "r"(srcbytes));
}
#define CP_COMMIT    asm volatile("cp.async.commit_group;")
#define CP_WAIT_1    asm volatile("cp.async.wait_group 1;")
#define CP_WAIT_0    asm volatile("cp.async.wait_group 0;")
#define CP_WAIT_ALL  asm volatile("cp.async.wait_all;")

// ---------------------------------------------------------------------------
// K1: FUSED QKV projection + attention. K=100 fully smem-resident.
// Block 384 thr (12 warps): warp = proj (w>>2) x m-slice ((w&3)*16).
// Tile: 64 rows x 32 ns-cols x 3 proj. smem row-major pitch 108.
// grid (64 ns, 16 rowtiles). Dynamic smem 69120 B.
// ---------------------------------------------------------------------------
__global__ __launch_bounds__(384) void qkv_attn(
        const float* __restrict__ edges,
        const float* __restrict__ wq, const float* __restrict__ bq,
        const float* __restrict__ wk, const float* __restrict__ bk,
        const float* __restrict__ wv, const float* __restrict__ bv,
        const float* __restrict__ qcw, const float* __restrict__ qcb,
        const float* __restrict__ kcw, const float* __restrict__ kcb,
        const float* __restrict__ vcw, const float* __restrict__ vcb)
{
    extern __shared__ float smem[];
    float* A = smem;                 // [64][108]
    float* B = smem + 64 * 108;      // [96][108]  (3 proj x 32 cols)
    float* sq = smem;                // union with A: [64][33] x3 = 6336 <= 6912
    float* sk = smem + 2112;
    float* sv = smem + 4224;

    const int t    = threadIdx.x;
    const int lane = t & 31;
    const int wid  = t >> 5;
    const int tig  = lane & 3;
    const int gid  = lane >> 2;

    const int ns   = blockIdx.x;
    const int row0 = blockIdx.y * 64;

    const int pw = wid >> 2;
    const int m0 = (wid & 3) * 16;

    // ---- load whole K (25 float4 per row) via cp.async ----
    for (int idx = t; idx < 1600; idx += 384) {         // A: 64 x 25
        int r = idx / 25, q = idx - r * 25;
        cp16(sa(A + r * 108 + q * 4), edges + (row0 + r) * DM + q * 4);
    }
    for (int idx = t; idx < 2400; idx += 384) {         // B: 96 x 25
        int rr = idx / 25, q = idx - rr * 25;
        int p = rr >> 5, n = rr & 31;
        const float* W = (p == 0) ? wq : (p == 1) ? wk : wv;
        cp16(sa(B + rr * 108 + q * 4), W + (ns * 32 + n) * DM + q * 4);
    }
    CP_COMMIT; CP_WAIT_ALL;
    // zero-pad k = 100..103
    for (int idx = t; idx < 160; idx += 384) {
        float* ptr = smem + idx * 108 + 100;
        ptr[0] = 0.0f; ptr[1] = 0.0f; ptr[2] = 0.0f; ptr[3] = 0.0f;
    }
    __syncthreads();

    // ---- MMA: 13 k-steps, no intervening barriers ----
    float acc[4][4] = {};
    #pragma unroll
    for (int ks = 0; ks < 13; ks++) {
        const int k0 = ks * 8;
        unsigned a0 = f2tf(A[(m0 + gid) * 108 + k0 + tig]);
        unsigned a1 = f2tf(A[(m0 + gid + 8) * 108 + k0 + tig]);
        unsigned a2 = f2tf(A[(m0 + gid) * 108 + k0 + tig + 4]);
        unsigned a3 = f2tf(A[(m0 + gid + 8) * 108 + k0 + tig + 4]);
        #pragma unroll
        for (int j = 0; j < 4; j++) {
            const int brow = pw * 32 + j * 8 + gid;
            unsigned b0 = f2tf(B[brow * 108 + k0 + tig]);
            unsigned b1 = f2tf(B[brow * 108 + k0 + tig + 4]);
            mma_tf32(acc[j], a0, a1, a2, a3, b0, b1);
        }
    }

    __syncthreads();   // done reading A before union overwrite

    // ---- epilogue: affine + bias -> sq/sk/sv ----
    {
        const float scale = (pw == 0) ? *qcw : (pw == 1) ? *kcw : *vcw;
        const float shift = (pw == 0) ? *qcb : (pw == 1) ? *kcb : *vcb;
        const float* bias = (pw == 0) ? bq : (pw == 1) ? bk : bv;
        float* sX = (pw == 0) ? sq : (pw == 1) ? sk : sv;

        #pragma unroll
        for (int j = 0; j < 4; j++) {
            const int col = j * 8 + 2 * tig;
            const float b0v = bias[ns * 32 + col];
            const float b1v = bias[ns * 32 + col + 1];
            const int r0 = m0 + gid;
            sX[r0 * 33 + col]           = fmaf(scale, acc[j][0] + b0v, shift);
            sX[r0 * 33 + col + 1]       = fmaf(scale, acc[j][1] + b1v, shift);
            sX[(r0 + 8) * 33 + col]     = fmaf(scale, acc[j][2] + b0v, shift);
            sX[(r0 + 8) * 33 + col + 1] = fmaf(scale, acc[j][3] + b1v, shift);
        }
    }
    __syncthreads();

    // ---- attention: 2048 items = 32 batches x 64 flats ----
    for (int idx = t; idx < 2048; idx += 384) {
        const int bloc = idx >> 6;
        const int lt   = idx & 63;
        const int rb   = 2 * bloc;
        const int w    = lt & 1;
        const int h    = lt >> 1;

        const float q = sq[(rb + (lt >> 5)) * 33 + (lt & 31)];

        float e[32];
        #pragma unroll
        for (int g = 0; g < 32; g++) {
            int f = 2 * g + w;
            e[g] = (g == h) ? -1e30f
                            : q * sk[(rb + (f >> 5)) * 33 + (f & 31)];
        }
        const int f0 = lt & ~1;
        const float ew0 = q * sk[(rb + (f0 >> 5)) * 33 + (f0 & 31)];
        const float ew1 = q * sk[(rb + ((f0 + 1) >> 5)) * 33 + ((f0 + 1) & 31)];

        float p0 = __expf(ew0);
        float p1 = __expf(ew1);
        float Z   = p0 + p1;
        float acc2 = p0 * sv[(rb + (f0 >> 5)) * 33 + (f0 & 31)]
                   + p1 * sv[(rb + ((f0 + 1) >> 5)) * 33 + ((f0 + 1) & 31)];
        #pragma unroll
        for (int g = 0; g < 32; g++) {
            int f = 2 * g + w;
            float pz = __expf(e[g]);
            Z   += pz;
            acc2 = fmaf(pz, sv[(rb + (f >> 5)) * 33 + (f & 31)], acc2);
        }
        const float o = acc2 / Z;
        const int grow = row0 + rb + (lt >> 5);
        g_att[grow * NSDK + ns * 32 + (lt & 31)] = o;
    }
}

// ---------------------------------------------------------------------------
// K2: fc GEMM split-K (tf32), double-buffered cp.async pipeline.
// Tile 64(M) x 112(N), chunks of 64 K. grid (16, 8); 128 thr.
// Dynamic smem 95744 B.
// ---------------------------------------------------------------------------
__global__ __launch_bounds__(128) void fc_tc(const float* __restrict__ fcw)
{
    extern __shared__ float smem[];
    // layout: buf b at offset b*11968: A[64][68] then B[112][68]

    const int t    = threadIdx.x;
    const int lane = t & 31;
    const int wid  = t >> 5;
    const int tig  = lane & 3;
    const int gid  = lane >> 2;

    const int row0 = blockIdx.x * 64;
    const int ks   = blockIdx.y;

    const int wm0 = (wid >> 1) * 32;
    const int wn0 = (wid & 1) * 56;

    float acc[2][7][4] = {};

    // load chunk c into buffer buf
    auto load_chunk = [&](int c, int buf) {
        const int kb = ks * 256 + c * 64;
        float* A = smem + buf * 11968;
        float* B = A + 4352;
        for (int idx = t; idx < 1024; idx += 128) {      // A: 64 x 16 f4
            int r = idx >> 4, q = idx & 15;
            cp16(sa(A + r * 68 + q * 4), g_att + (row0 + r) * NSDK + kb + q * 4);
        }
        for (int idx = t; idx < 1792; idx += 128) {      // B: 112 x 16 f4
            int r = idx >> 4, q = idx & 15;
            int rc = (r < DM) ? r : (DM - 1);
            cp16z(sa(B + r * 68 + q * 4), fcw + rc * NSDK + kb + q * 4,
                  (r < DM) ? 16 : 0);
        }
        CP_COMMIT;
    };

    load_chunk(0, 0);

    for (int c = 0; c < 4; c++) {
        if (c < 3) load_chunk(c + 1, (c + 1) & 1);
        if (c < 3) { CP_WAIT_1; } else { CP_WAIT_0; }
        __syncthreads();

        const float* A = smem + (c & 1) * 11968;
        const float* B = A + 4352;

        #pragma unroll
        for (int kss = 0; kss < 8; kss++) {
            const int k0 = kss * 8;
            unsigned a[2][4];
            #pragma unroll
            for (int i = 0; i < 2; i++) {
                int mb = wm0 + i * 16;
                a[i][0] = f2tf(A[(mb + gid) * 68 + k0 + tig]);
                a[i][1] = f2tf(A[(mb + gid + 8) * 68 + k0 + tig]);
                a[i][2] = f2tf(A[(mb + gid) * 68 + k0 + tig + 4]);
                a[i][3] = f2tf(A[(mb + gid + 8) * 68 + k0 + tig + 4]);
            }
            #pragma unroll
            for (int j = 0; j < 7; j++) {
                const int brow = wn0 + j * 8 + gid;
                unsigned b0 = f2tf(B[brow * 68 + k0 + tig]);
                unsigned b1 = f2tf(B[brow * 68 + k0 + tig + 4]);
                #pragma unroll
                for (int i = 0; i < 2; i++)
                    mma_tf32(acc[i][j], a[i][0], a[i][1], a[i][2], a[i][3], b0, b1);
            }
        }
        __syncthreads();
    }

    #pragma unroll
    for (int i = 0; i < 2; i++) {
        #pragma unroll
        for (int j = 0; j < 7; j++) {
            const int col = wn0 + j * 8 + 2 * tig;
            if (col < DM) {
                int r0 = row0 + wm0 + i * 16 + gid;
                *(float2*)&g_part[ks * PART_STRIDE + r0 * DM + col] =
                    make_float2(acc[i][j][0], acc[i][j][1]);
                *(float2*)&g_part[ks * PART_STRIDE + (r0 + 8) * DM + col] =
                    make_float2(acc[i][j][2], acc[i][j][3]);
            }
        }
    }
}

// ---------------------------------------------------------------------------
// K3: reduce partials + bias + residual + LayerNorm1. Warp per row.
// ---------------------------------------------------------------------------
__global__ void ln1_kernel(const float* __restrict__ edges,
                           const float* __restrict__ fcb,
                           const float* __restrict__ g1,
                           const float* __restrict__ b1)
{
    const int wid  = threadIdx.x >> 5;
    const int lane = threadIdx.x & 31;
    const int row  = blockIdx.x * 8 + wid;

    float x[4];
    #pragma unroll
    for (int i = 0; i < 4; i++) {
        int c = lane + i * 32;
        float v = 0.0f;
        if (c < DM) {
            v = fcb[c] + edges[row * DM + c];
            #pragma unroll
            for (int s = 0; s < KSPLIT; s++)
                v += g_part[s * PART_STRIDE + row * DM + c];
        }
        x[i] = v;
    }

    float s = x[0] + x[1] + x[2] + x[3];
    #pragma unroll
    for (int off = 16; off > 0; off >>= 1) s += __shfl_xor_sync(0xffffffffu, s, off);
    const float mean = s * (1.0f / DM);

    float v2 = 0.0f;
    #pragma unroll
    for (int i = 0; i < 4; i++) {
        int c = lane + i * 32;
        if (c < DM) {
            float d = x[i] - mean;
            v2 = fmaf(d, d, v2);
        }
    }
    #pragma unroll
    for (int off = 16; off > 0; off >>= 1) v2 += __shfl_xor_sync(0xffffffffu, v2, off);
    const float inv = rsqrtf(v2 * (1.0f / DM) + 1e-5f);

    #pragma unroll
    for (int i = 0; i < 4; i++) {
        int c = lane + i * 32;
        if (c < DM)
            g_ln1[row * DM + c] = (x[i] - mean) * inv * g1[c] + b1[c];
    }
}

// ---------------------------------------------------------------------------
// K4: MLP layer 1 (tf32): h = relu(ln1 @ w1^T + b1). K=100 resident.
// Tile 32(M) x 128(N), grid (4, 32), 128 thr. Dynamic smem 69120 B.
// ---------------------------------------------------------------------------
__global__ __launch_bounds__(128) void mlp_l1_tc(const float* __restrict__ w1,
                                                 const float* __restrict__ b1)
{
    extern __shared__ float smem[];
    float* A = smem;                 // [32][108]
    float* B = smem + 32 * 108;      // [128][108]

    const int t    = threadIdx.x;
    const int lane = t & 31;
    const int wid  = t >> 5;
    const int tig  = lane & 3;
    const int gid  = lane >> 2;

    const int col0 = blockIdx.x * 128;
    const int row0 = blockIdx.y * 32;

    const int wm0 = (wid >> 1) * 16;
    const int wn0 = (wid & 1) * 64;

    for (int idx = t; idx < 800; idx += 128) {          // A: 32 x 25
        int r = idx / 25, q = idx - r * 25;
        cp16(sa(A + r * 108 + q * 4), g_ln1 + (row0 + r) * DM + q * 4);
    }
    for (int idx = t; idx < 3200; idx += 128) {         // B: 128 x 25
        int r = idx / 25, q = idx - r * 25;
        int gc = col0 + r;
        int rc = (gc < DI_) ? gc : (DI_ - 1);
        cp16z(sa(B + r * 108 + q * 4), w1 + rc * DM + q * 4,
              (gc < DI_) ? 16 : 0);
    }
    CP_COMMIT; CP_WAIT_ALL;
    for (int idx = t; idx < 160; idx += 128) {          // zero-pad k 100..103
        float* ptr = smem + idx * 108 + 100;
        ptr[0] = 0.0f; ptr[1] = 0.0f; ptr[2] = 0.0f; ptr[3] = 0.0f;
    }
    __syncthreads();

    float acc[8][4] = {};
    #pragma unroll
    for (int ks = 0; ks < 13; ks++) {
        const int k0 = ks * 8;
        unsigned a0 = f2tf(A[(wm0 + gid) * 108 + k0 + tig]);
        unsigned a1 = f2tf(A[(wm0 + gid + 8) * 108 + k0 + tig]);
        unsigned a2 = f2tf(A[(wm0 + gid) * 108 + k0 + tig + 4]);
        unsigned a3 = f2tf(A[(wm0 + gid + 8) * 108 + k0 + tig + 4]);
        #pragma unroll
        for (int j = 0; j < 8; j++) {
            const int brow = wn0 + j * 8 + gid;
            unsigned b0 = f2tf(B[brow * 108 + k0 + tig]);
            unsigned b1 = f2tf(B[brow * 108 + k0 + tig + 4]);
            mma_tf32(acc[j], a0, a1, a2, a3, b0, b1);
        }
    }

    #pragma unroll
    for (int j = 0; j < 8; j++) {
        const int colg = col0 + wn0 + j * 8 + 2 * tig;
        if (colg < DI_) {
            const float b0v = b1[colg];
            const float b1v = b1[colg + 1];
            int r0 = row0 + wm0 + gid;
            float2 v0, v1;
            v0.x = fmaxf(acc[j][0] + b0v, 0.0f);
            v0.y = fmaxf(acc[j][1] + b1v, 0.0f);
            v1.x = fmaxf(acc[j][2] + b0v, 0.0f);
            v1.y = fmaxf(acc[j][3] + b1v, 0.0f);
            *(float2*)&g_h[r0 * DI_ + colg]       = v0;
            *(float2*)&g_h[(r0 + 8) * DI_ + colg] = v1;
        }
    }
}

// ---------------------------------------------------------------------------
// K5: MLP layer 2 (tf32) + bias + residual + LN2 -> d_out.
// Tile 16(M) x 128(N), chunks of 64 K (7, zfill past 400), double-buffered.
// grid 64, 128 thr (4 warps, 32 N each). Dynamic smem 78336 B.
// ---------------------------------------------------------------------------
__global__ __launch_bounds__(128) void mlp_l2_tc(const float* __restrict__ w2,
                                                 const float* __restrict__ b2,
                                                 const float* __restrict__ g2,
                                                 const float* __restrict__ bb2,
                                                 float* __restrict__ outp)
{
    extern __shared__ float smem[];
    // buf b at offset b*9792: A[16][68] (1088) then B[128][68] (8704)

    const int t    = threadIdx.x;
    const int lane = t & 31;
    const int wid  = t >> 5;
    const int tig  = lane & 3;
    const int gid  = lane >> 2;

    const int row0 = blockIdx.x * 16;
    const int wn0  = wid * 32;

    float acc[4][4] = {};

    auto load_chunk = [&](int c, int buf) {
        const int kb = c * 64;
        float* A = smem + buf * 9792;
        float* B = A + 1088;
        for (int idx = t; idx < 256; idx += 128) {       // A: 16 x 16 f4
            int r = idx >> 4, q = idx & 15;
            int k = kb + q * 4;
            cp16z(sa(A + r * 68 + q * 4),
                  g_h + (row0 + r) * DI_ + ((k < DI_) ? k : 0),
                  (k < DI_) ? 16 : 0);
        }
        for (int idx = t; idx < 2048; idx += 128) {      // B: 128 x 16 f4
            int r = idx >> 4, q = idx & 15;
            int k = kb + q * 4;
            int ok = (r < DM) && (k < DI_);
            cp16z(sa(B + r * 68 + q * 4),
                  w2 + ((r < DM) ? r : 0) * DI_ + ((k < DI_) ? k : 0),
                  ok ? 16 : 0);
        }
        CP_COMMIT;
    };

    load_chunk(0, 0);

    for (int c = 0; c < 7; c++) {
        if (c < 6) load_chunk(c + 1, (c + 1) & 1);
        if (c < 6) { CP_WAIT_1; } else { CP_WAIT_0; }
        __syncthreads();

        const float* A = smem + (c & 1) * 9792;
        const float* B = A + 1088;

        #pragma unroll
        for (int kss = 0; kss < 8; kss++) {
            const int k0 = kss * 8;
            unsigned a0 = f2tf(A[gid * 68 + k0 + tig]);
            unsigned a1 = f2tf(A[(gid + 8) * 68 + k0 + tig]);
            unsigned a2 = f2tf(A[gid * 68 + k0 + tig + 4]);
            unsigned a3 = f2tf(A[(gid + 8) * 68 + k0 + tig + 4]);
            #pragma unroll
            for (int j = 0; j < 4; j++) {
                const int brow = wn0 + j * 8 + gid;
                unsigned b0 = f2tf(B[brow * 68 + k0 + tig]);
                unsigned b1 = f2tf(B[brow * 68 + k0 + tig + 4]);
                mma_tf32(acc[j], a0, a1, a2, a3, b0, b1);
            }
        }
        __syncthreads();
    }

    // stage results in smem (reuse buffers), then fused LN2
    float* ys = smem;                // [16][132]
    #pragma unroll
    for (int j = 0; j < 4; j++) {
        const int col = wn0 + j * 8 + 2 * tig;
        ys[gid * 132 + col]           = acc[j][0];
        ys[gid * 132 + col + 1]       = acc[j][1];
        ys[(gid + 8) * 132 + col]     = acc[j][2];
        ys[(gid + 8) * 132 + col + 1] = acc[j][3];
    }
    __syncthreads();

    if (t < 64) {
        const int r    = t >> 2;
        const int s4   = t & 3;
        const int grow = row0 + r;

        float vals[25];
        float sum = 0.0f;
        #pragma unroll
        for (int j = 0; j < 25; j++) {
            int c = s4 + 4 * j;
            float v = ys[r * 132 + c] + b2[c] + g_ln1[grow * DM + c];
            vals[j] = v;
            sum += v;
        }
        sum += __shfl_xor_sync(0xffffffffu, sum, 1);
        sum += __shfl_xor_sync(0xffffffffu, sum, 2);
        const float mean = sum * (1.0f / DM);

        float v2 = 0.0f;
        #pragma unroll
        for (int j = 0; j < 25; j++) {
            float d = vals[j] - mean;
            v2 = fmaf(d, d, v2);
        }
        v2 += __shfl_xor_sync(0xffffffffu, v2, 1);
        v2 += __shfl_xor_sync(0xffffffffu, v2, 2);
        const float inv = rsqrtf(v2 * (1.0f / DM) + 1e-5f);

        #pragma unroll
        for (int j = 0; j < 25; j++) {
            int c = s4 + 4 * j;
            outp[grow * DM + c] = (vals[j] - mean) * inv * g2[c] + bb2[c];
        }
    }
}

// ---------------------------------------------------------------------------
extern "C" void kernel_launch(void* const* d_in, const int* in_sizes, int n_in,
                              void* d_out, int out_size)
{
    (void)in_sizes; (void)n_in; (void)out_size;
    const float* edges = (const float*)d_in[0];
    const float* wq    = (const float*)d_in[1];
    const float* bq    = (const float*)d_in[2];
    const float* wk    = (const float*)d_in[3];
    const float* bk    = (const float*)d_in[4];
    const float* wv    = (const float*)d_in[5];
    const float* bv    = (const float*)d_in[6];
    const float* qcw   = (const float*)d_in[7];
    const float* qcb   = (const float*)d_in[8];
    const float* kcw   = (const float*)d_in[9];
    const float* kcb   = (const float*)d_in[10];
    const float* vcw   = (const float*)d_in[11];
    const float* vcb   = (const float*)d_in[12];
    const float* fcw   = (const float*)d_in[13];
    const float* fcb   = (const float*)d_in[14];
    const float* ln1g  = (const float*)d_in[15];
    const float* ln1b  = (const float*)d_in[16];
    const float* w1w   = (const float*)d_in[17];
    const float* w1b   = (const float*)d_in[18];
    const float* w2w   = (const float*)d_in[19];
    const float* w2b   = (const float*)d_in[20];
    const float* ln2g  = (const float*)d_in[21];
    const float* ln2b  = (const float*)d_in[22];

    static const int smem_qkv = 69120;
    static const int smem_fc  = 95744;
    static const int smem_l1  = 69120;
    static const int smem_l2  = 78336;
    cudaFuncSetAttribute(qkv_attn, cudaFuncAttributeMaxDynamicSharedMemorySize, smem_qkv);
    cudaFuncSetAttribute(fc_tc,    cudaFuncAttributeMaxDynamicSharedMemorySize, smem_fc);
    cudaFuncSetAttribute(mlp_l1_tc,cudaFuncAttributeMaxDynamicSharedMemorySize, smem_l1);
    cudaFuncSetAttribute(mlp_l2_tc,cudaFuncAttributeMaxDynamicSharedMemorySize, smem_l2);

    qkv_attn<<<dim3(64, 16), 384, smem_qkv>>>(edges, wq, bq, wk, bk, wv, bv,
                                              qcw, qcb, kcw, kcb, vcw, vcb);
    fc_tc<<<dim3(16, KSPLIT), 128, smem_fc>>>(fcw);
    ln1_kernel<<<ROWS / 8, 256>>>(edges, fcb, ln1g, ln1b);
    mlp_l1_tc<<<dim3(4, 32), 128, smem_l1>>>(w1w, w1b);
    mlp_l2_tc<<<64, 128, smem_l2>>>(w2w, w2b, ln2g, ln2b, (float*)d_out);
}

// round 6
// speedup vs baseline: 1.5789x; 1.0108x over previous
#include <cuda_runtime.h>

// Problem constants
#define DM    100
#define NSDK  2048
#define ROWS  1024        // SZ_B * L
#define DI_   400
#define KSPLIT 8
#define PART_STRIDE (ROWS * DM)

// Scratch (device globals — no allocation)
__device__ float g_att[ROWS * NSDK];          // attention output [1024][2048]
__device__ float g_part[KSPLIT * PART_STRIDE];// fc split-K partials

// ---------------------------------------------------------------------------
// helpers
// ---------------------------------------------------------------------------
__device__ __forceinline__ unsigned f2tf(float v) {
    unsigned r;
    asm("cvt.rna.tf32.f32 %0, %1;" : "=r"(r) : "f"(v));
    return r;
}

__device__ __forceinline__ void mma_tf32(float c[4],
                                         unsigned a0, unsigned a1, unsigned a2, unsigned a3,
                                         unsigned b0, unsigned b1) {
    asm("mma.sync.aligned.m16n8k8.row.col.f32.tf32.tf32.f32 "
        "{%0,%1,%2,%3},{%4,%5,%6,%7},{%8,%9},{%0,%1,%2,%3};"
        : "+f"(c[0]), "+f"(c[1]), "+f"(c[2]), "+f"(c[3])
        : "r"(a0), "r"(a1), "r"(a2), "r"(a3), "r"(b0), "r"(b1));
}

__device__ __forceinline__ unsigned sa(const void* p) {
    return (unsigned)__cvta_generic_to_shared(p);
}
__device__ __forceinline__ void cp16(unsigned d, const void* s) {
    asm volatile("cp.async.ca.shared.global [%0], [%1], 16;" :: "r"(d), "l"(s));
}
__device__ __forceinline__ void cp16z(unsigned d, const void* s, int srcbytes) {
    asm volatile("cp.async.ca.shared.global [%0], [%1], 16, %2;"
                 :: "r"(d), "l"(s), "r"(srcbytes));
}
#define CP_COMMIT    asm volatile("cp.async.commit_group;")
#define CP_WAIT_1    asm volatile("cp.async.wait_group 1;")
#define CP_WAIT_0    asm volatile("cp.async.wait_group 0;")
#define CP_WAIT_ALL  asm volatile("cp.async.wait_all;")

// ---------------------------------------------------------------------------
// K1: FUSED QKV projection + attention. K=100 fully smem-resident.
// Block 384 thr (12 warps): warp = proj (w>>2) x m-slice ((w&3)*16).
// grid (64 ns, 16 rowtiles). Dynamic smem 69120 B.
// ---------------------------------------------------------------------------
__global__ __launch_bounds__(384) void qkv_attn(
        const float* __restrict__ edges,
        const float* __restrict__ wq, const float* __restrict__ bq,
        const float* __restrict__ wk, const float* __restrict__ bk,
        const float* __restrict__ wv, const float* __restrict__ bv,
        const float* __restrict__ qcw, const float* __restrict__ qcb,
        const float* __restrict__ kcw, const float* __restrict__ kcb,
        const float* __restrict__ vcw, const float* __restrict__ vcb)
{
    extern __shared__ float smem[];
    float* A = smem;                 // [64][108]
    float* B = smem + 64 * 108;      // [96][108]
    float* sq = smem;                // union with A: [64][33] x3
    float* sk = smem + 2112;
    float* sv = smem + 4224;

    const int t    = threadIdx.x;
    const int lane = t & 31;
    const int wid  = t >> 5;
    const int tig  = lane & 3;
    const int gid  = lane >> 2;

    const int ns   = blockIdx.x;
    const int row0 = blockIdx.y * 64;

    const int pw = wid >> 2;
    const int m0 = (wid & 3) * 16;

    for (int idx = t; idx < 1600; idx += 384) {
        int r = idx / 25, q = idx - r * 25;
        cp16(sa(A + r * 108 + q * 4), edges + (row0 + r) * DM + q * 4);
    }
    for (int idx = t; idx < 2400; idx += 384) {
        int rr = idx / 25, q = idx - rr * 25;
        int p = rr >> 5, n = rr & 31;
        const float* W = (p == 0) ? wq : (p == 1) ? wk : wv;
        cp16(sa(B + rr * 108 + q * 4), W + (ns * 32 + n) * DM + q * 4);
    }
    CP_COMMIT; CP_WAIT_ALL;
    for (int idx = t; idx < 160; idx += 384) {
        float* ptr = smem + idx * 108 + 100;
        ptr[0] = 0.0f; ptr[1] = 0.0f; ptr[2] = 0.0f; ptr[3] = 0.0f;
    }
    __syncthreads();

    float acc[4][4] = {};
    #pragma unroll
    for (int ks = 0; ks < 13; ks++) {
        const int k0 = ks * 8;
        unsigned a0 = f2tf(A[(m0 + gid) * 108 + k0 + tig]);
        unsigned a1 = f2tf(A[(m0 + gid + 8) * 108 + k0 + tig]);
        unsigned a2 = f2tf(A[(m0 + gid) * 108 + k0 + tig + 4]);
        unsigned a3 = f2tf(A[(m0 + gid + 8) * 108 + k0 + tig + 4]);
        #pragma unroll
        for (int j = 0; j < 4; j++) {
            const int brow = pw * 32 + j * 8 + gid;
            unsigned b0 = f2tf(B[brow * 108 + k0 + tig]);
            unsigned b1 = f2tf(B[brow * 108 + k0 + tig + 4]);
            mma_tf32(acc[j], a0, a1, a2, a3, b0, b1);
        }
    }

    __syncthreads();

    {
        const float scale = (pw == 0) ? *qcw : (pw == 1) ? *kcw : *vcw;
        const float shift = (pw == 0) ? *qcb : (pw == 1) ? *kcb : *vcb;
        const float* bias = (pw == 0) ? bq : (pw == 1) ? bk : bv;
        float* sX = (pw == 0) ? sq : (pw == 1) ? sk : sv;

        #pragma unroll
        for (int j = 0; j < 4; j++) {
            const int col = j * 8 + 2 * tig;
            const float b0v = bias[ns * 32 + col];
            const float b1v = bias[ns * 32 + col + 1];
            const int r0 = m0 + gid;
            sX[r0 * 33 + col]           = fmaf(scale, acc[j][0] + b0v, shift);
            sX[r0 * 33 + col + 1]       = fmaf(scale, acc[j][1] + b1v, shift);
            sX[(r0 + 8) * 33 + col]     = fmaf(scale, acc[j][2] + b0v, shift);
            sX[(r0 + 8) * 33 + col + 1] = fmaf(scale, acc[j][3] + b1v, shift);
        }
    }
    __syncthreads();

    for (int idx = t; idx < 2048; idx += 384) {
        const int bloc = idx >> 6;
        const int lt   = idx & 63;
        const int rb   = 2 * bloc;
        const int w    = lt & 1;
        const int h    = lt >> 1;

        const float q = sq[(rb + (lt >> 5)) * 33 + (lt & 31)];

        float e[32];
        #pragma unroll
        for (int g = 0; g < 32; g++) {
            int f = 2 * g + w;
            e[g] = (g == h) ? -1e30f
                            : q * sk[(rb + (f >> 5)) * 33 + (f & 31)];
        }
        const int f0 = lt & ~1;
        const float ew0 = q * sk[(rb + (f0 >> 5)) * 33 + (f0 & 31)];
        const float ew1 = q * sk[(rb + ((f0 + 1) >> 5)) * 33 + ((f0 + 1) & 31)];

        float p0 = __expf(ew0);
        float p1 = __expf(ew1);
        float Z   = p0 + p1;
        float acc2 = p0 * sv[(rb + (f0 >> 5)) * 33 + (f0 & 31)]
                   + p1 * sv[(rb + ((f0 + 1) >> 5)) * 33 + ((f0 + 1) & 31)];
        #pragma unroll
        for (int g = 0; g < 32; g++) {
            int f = 2 * g + w;
            float pz = __expf(e[g]);
            Z   += pz;
            acc2 = fmaf(pz, sv[(rb + (f >> 5)) * 33 + (f & 31)], acc2);
        }
        const float o = acc2 / Z;
        const int grow = row0 + rb + (lt >> 5);
        g_att[grow * NSDK + ns * 32 + (lt & 31)] = o;
    }
}

// ---------------------------------------------------------------------------
// K2: fc GEMM split-K (tf32), double-buffered cp.async, 256 threads (8 warps:
// 4M x 2N, warp tile 16x56). Tile 64(M) x 112(N), 4 chunks of K=64.
// grid (16, 8). Dynamic smem 95744 B.
// ---------------------------------------------------------------------------
__global__ __launch_bounds__(256) void fc_tc(const float* __restrict__ fcw)
{
    extern __shared__ float smem[];
    // buf b at offset b*11968: A[64][68] then B[112][68]

    const int t    = threadIdx.x;
    const int lane = t & 31;
    const int wid  = t >> 5;
    const int tig  = lane & 3;
    const int gid  = lane >> 2;

    const int row0 = blockIdx.x * 64;
    const int ks   = blockIdx.y;

    const int wm0 = (wid >> 1) * 16;
    const int wn0 = (wid & 1) * 56;

    float acc[7][4] = {};

    auto load_chunk = [&](int c, int buf) {
        const int kb = ks * 256 + c * 64;
        float* A = smem + buf * 11968;
        float* B = A + 4352;
        for (int idx = t; idx < 1024; idx += 256) {
            int r = idx >> 4, q = idx & 15;
            cp16(sa(A + r * 68 + q * 4), g_att + (row0 + r) * NSDK + kb + q * 4);
        }
        for (int idx = t; idx < 1792; idx += 256) {
            int r = idx >> 4, q = idx & 15;
            int rc = (r < DM) ? r : (DM - 1);
            cp16z(sa(B + r * 68 + q * 4), fcw + rc * NSDK + kb + q * 4,
                  (r < DM) ? 16 : 0);
        }
        CP_COMMIT;
    };

    load_chunk(0, 0);

    for (int c = 0; c < 4; c++) {
        if (c < 3) load_chunk(c + 1, (c + 1) & 1);
        if (c < 3) { CP_WAIT_1; } else { CP_WAIT_0; }
        __syncthreads();

        const float* A = smem + (c & 1) * 11968;
        const float* B = A + 4352;

        #pragma unroll
        for (int kss = 0; kss < 8; kss++) {
            const int k0 = kss * 8;
            unsigned a0 = f2tf(A[(wm0 + gid) * 68 + k0 + tig]);
            unsigned a1 = f2tf(A[(wm0 + gid + 8) * 68 + k0 + tig]);
            unsigned a2 = f2tf(A[(wm0 + gid) * 68 + k0 + tig + 4]);
            unsigned a3 = f2tf(A[(wm0 + gid + 8) * 68 + k0 + tig + 4]);
            #pragma unroll
            for (int j = 0; j < 7; j++) {
                const int brow = wn0 + j * 8 + gid;
                unsigned b0 = f2tf(B[brow * 68 + k0 + tig]);
                unsigned b1 = f2tf(B[brow * 68 + k0 + tig + 4]);
                mma_tf32(acc[j], a0, a1, a2, a3, b0, b1);
            }
        }
        __syncthreads();
    }

    #pragma unroll
    for (int j = 0; j < 7; j++) {
        const int col = wn0 + j * 8 + 2 * tig;
        if (col < DM) {
            int r0 = row0 + wm0 + gid;
            *(float2*)&g_part[ks * PART_STRIDE + r0 * DM + col] =
                make_float2(acc[j][0], acc[j][1]);
            *(float2*)&g_part[ks * PART_STRIDE + (r0 + 8) * DM + col] =
                make_float2(acc[j][2], acc[j][3]);
        }
    }
}

// ---------------------------------------------------------------------------
// K3: FUSED tail: partials-reduce + LN1 + MLP-l1(relu) + MLP-l2 + LN2 -> out.
// 16 rows/block, grid 64, 256 threads (8 warps). All intermediates in smem.
// w1/w2 streamed in double-buffered cp.async chunks overlapped with compute.
// smem (floats): xs[16][108] @0, hs[16][420] @1728, R0 @8448, R1 @30912
//   (regions 22464 floats each). Total 53376 floats = 213504 B.
// ---------------------------------------------------------------------------
__global__ __launch_bounds__(256) void mlp_fused(
        const float* __restrict__ edges, const float* __restrict__ fcb,
        const float* __restrict__ ln1g,  const float* __restrict__ ln1b,
        const float* __restrict__ w1,    const float* __restrict__ w1b,
        const float* __restrict__ w2,    const float* __restrict__ w2b,
        const float* __restrict__ ln2g,  const float* __restrict__ ln2b,
        float* __restrict__ outp)
{
    extern __shared__ float smem[];
    float* xs  = smem;            // [16][108]  LN1 output (k-pad zeroed)
    float* hs  = smem + 1728;     // [16][420]  hidden (cols 400..415 zeroed)
    float* sR0 = smem + 8448;
    float* sR1 = smem + 30912;

    const int t    = threadIdx.x;
    const int lane = t & 31;
    const int wid  = t >> 5;
    const int tig  = lane & 3;
    const int gid  = lane >> 2;
    const int row0 = blockIdx.x * 16;

    // ---- w1 chunk loader: rows of w1 (N dim), K=100 resident, pitch 108 ----
    auto cp_w1 = [&](int chunk, float* R) {
        const int rows = chunk ? 192 : 208;
        const int base = chunk * 208;
        for (int idx = t; idx < rows * 26; idx += 256) {
            int r = idx / 26, q = idx - r * 26;
            if (q < 25)
                cp16(sa(R + r * 108 + q * 4), w1 + (base + r) * DM + q * 4);
            else
                cp16z(sa(R + r * 108 + 100), w1, 0);   // zero k-pad 100..103
        }
        CP_COMMIT;
    };

    // ---- w2 chunk loader: [104 rows][208 K-cols], pitch 212 ----
    auto cp_w2 = [&](int chunk, float* R) {
        const int kbase = chunk * 208;
        for (int idx = t; idx < 104 * 52; idx += 256) {
            int r = idx / 52, q = idx - r * 52;
            int k = kbase + q * 4;
            int ok = (r < DM) && (k + 4 <= DI_);
            cp16z(sa(R + r * 212 + q * 4),
                  w2 + (ok ? r * DI_ + k : 0), ok ? 16 : 0);
        }
        CP_COMMIT;
    };

    // ================== pipeline ==================
    cp_w1(0, sR0);                                   // G0 (overlaps phase 1)

    // ---- phase 1: reduce fc partials + bias + residual -> xs (raw) ----
    for (int idx = t; idx < 1600; idx += 256) {
        int r = idx / 100, c = idx - r * 100;
        int grow = row0 + r;
        float v = fcb[c] + edges[grow * DM + c];
        #pragma unroll
        for (int s = 0; s < KSPLIT; s++)
            v += g_part[s * PART_STRIDE + grow * DM + c];
        xs[r * 108 + c] = v;
    }
    __syncthreads();

    // ---- LN1 in place (quad per row, t<64) + zero k-pad ----
    if (t < 64) {
        const int r = t >> 2, s4 = t & 3;
        float vals[25];
        float sum = 0.0f;
        #pragma unroll
        for (int j = 0; j < 25; j++) {
            float v = xs[r * 108 + s4 + 4 * j];
            vals[j] = v;  sum += v;
        }
        sum += __shfl_xor_sync(0xffffffffu, sum, 1);
        sum += __shfl_xor_sync(0xffffffffu, sum, 2);
        const float mean = sum * (1.0f / DM);
        float v2 = 0.0f;
        #pragma unroll
        for (int j = 0; j < 25; j++) {
            float d = vals[j] - mean;
            v2 = fmaf(d, d, v2);
        }
        v2 += __shfl_xor_sync(0xffffffffu, v2, 1);
        v2 += __shfl_xor_sync(0xffffffffu, v2, 2);
        const float inv = rsqrtf(v2 * (1.0f / DM) + 1e-5f);
        #pragma unroll
        for (int j = 0; j < 25; j++) {
            int c = s4 + 4 * j;
            xs[r * 108 + c] = (vals[j] - mean) * inv * ln1g[c] + ln1b[c];
        }
        if (s4 == 0) {   // zero k-pad cols 100..103
            xs[r * 108 + 100] = 0.0f; xs[r * 108 + 101] = 0.0f;
            xs[r * 108 + 102] = 0.0f; xs[r * 108 + 103] = 0.0f;
        }
    }

    cp_w1(1, sR1);                                   // G1
    CP_WAIT_1; __syncthreads();                      // G0 done; xs visible

    // ---- layer 1 (chunk version) ----
    auto layer1_chunk = [&](int chunk, const float* R) {
        const int nfr = chunk ? 24 : 26;
        const int nmy = (nfr - wid + 7) >> 3;
        const int nbg = chunk * 208;
        float acc[4][4] = {};
        #pragma unroll
        for (int ks = 0; ks < 13; ks++) {
            const int k0 = ks * 8;
            unsigned a0 = f2tf(xs[gid * 108 + k0 + tig]);
            unsigned a1 = f2tf(xs[(gid + 8) * 108 + k0 + tig]);
            unsigned a2 = f2tf(xs[gid * 108 + k0 + tig + 4]);
            unsigned a3 = f2tf(xs[(gid + 8) * 108 + k0 + tig + 4]);
            #pragma unroll
            for (int j = 0; j < 4; j++) {
                if (j < nmy) {
                    int brow = (wid + 8 * j) * 8 + gid;
                    unsigned b0 = f2tf(R[brow * 108 + k0 + tig]);
                    unsigned b1 = f2tf(R[brow * 108 + k0 + tig + 4]);
                    mma_tf32(acc[j], a0, a1, a2, a3, b0, b1);
                }
            }
        }
        #pragma unroll
        for (int j = 0; j < 4; j++) {
            if (j < nmy) {
                int cg = nbg + (wid + 8 * j) * 8 + 2 * tig;
                float bb0 = w1b[cg], bb1 = w1b[cg + 1];
                hs[gid * 420 + cg]           = fmaxf(acc[j][0] + bb0, 0.0f);
                hs[gid * 420 + cg + 1]       = fmaxf(acc[j][1] + bb1, 0.0f);
                hs[(gid + 8) * 420 + cg]     = fmaxf(acc[j][2] + bb0, 0.0f);
                hs[(gid + 8) * 420 + cg + 1] = fmaxf(acc[j][3] + bb1, 0.0f);
            }
        }
    };

    layer1_chunk(0, sR0);
    __syncthreads();                                 // R0 reads done
    cp_w2(0, sR0);                                   // G2
    CP_WAIT_1; __syncthreads();                      // G1 done
    layer1_chunk(1, sR1);
    {   // zero hs k-pad cols 400..415
        int r = t >> 4, c = 400 + (t & 15);
        hs[r * 420 + c] = 0.0f;
    }
    __syncthreads();                                 // R1 reads + hs complete
    cp_w2(1, sR1);                                   // G3
    CP_WAIT_1; __syncthreads();                      // G2 done

    // ---- layer 2: accumulate across 2 K-chunks ----
    const int nmy2 = (wid < 5) ? 2 : 1;
    float l2acc[2][4] = {};
    auto layer2_chunk = [&](int chunk, const float* R) {
        #pragma unroll 2
        for (int ks = 0; ks < 26; ks++) {
            const int k0 = ks * 8;
            const int kk = chunk * 208 + k0;
            unsigned a0 = f2tf(hs[gid * 420 + kk + tig]);
            unsigned a1 = f2tf(hs[(gid + 8) * 420 + kk + tig]);
            unsigned a2 = f2tf(hs[gid * 420 + kk + tig + 4]);
            unsigned a3 = f2tf(hs[(gid + 8) * 420 + kk + tig + 4]);
            #pragma unroll
            for (int j = 0; j < 2; j++) {
                if (j < nmy2) {
                    int brow = (wid + 8 * j) * 8 + gid;
                    unsigned b0 = f2tf(R[brow * 212 + k0 + tig]);
                    unsigned b1 = f2tf(R[brow * 212 + k0 + tig + 4]);
                    mma_tf32(l2acc[j], a0, a1, a2, a3, b0, b1);
                }
            }
        }
    };

    layer2_chunk(0, sR0);
    CP_WAIT_0; __syncthreads();                      // G3 done
    layer2_chunk(1, sR1);

    // ---- stage ys (reuse R0), then LN2 with residual xs ----
    __syncthreads();
    float* ys = sR0;                                 // [16][104]
    #pragma unroll
    for (int j = 0; j < 2; j++) {
        if (j < nmy2) {
            int col = (wid + 8 * j) * 8 + 2 * tig;
            ys[gid * 104 + col]           = l2acc[j][0];
            ys[gid * 104 + col + 1]       = l2acc[j][1];
            ys[(gid + 8) * 104 + col]     = l2acc[j][2];
            ys[(gid + 8) * 104 + col + 1] = l2acc[j][3];
        }
    }
    __syncthreads();

    if (t < 64) {
        const int r    = t >> 2;
        const int s4   = t & 3;
        const int grow = row0 + r;

        float vals[25];
        float sum = 0.0f;
        #pragma unroll
        for (int j = 0; j < 25; j++) {
            int c = s4 + 4 * j;
            float v = ys[r * 104 + c] + w2b[c] + xs[r * 108 + c];
            vals[j] = v;  sum += v;
        }
        sum += __shfl_xor_sync(0xffffffffu, sum, 1);
        sum += __shfl_xor_sync(0xffffffffu, sum, 2);
        const float mean = sum * (1.0f / DM);

        float v2 = 0.0f;
        #pragma unroll
        for (int j = 0; j < 25; j++) {
            float d = vals[j] - mean;
            v2 = fmaf(d, d, v2);
        }
        v2 += __shfl_xor_sync(0xffffffffu, v2, 1);
        v2 += __shfl_xor_sync(0xffffffffu, v2, 2);
        const float inv = rsqrtf(v2 * (1.0f / DM) + 1e-5f);

        #pragma unroll
        for (int j = 0; j < 25; j++) {
            int c = s4 + 4 * j;
            outp[grow * DM + c] = (vals[j] - mean) * inv * ln2g[c] + ln2b[c];
        }
    }
}

// ---------------------------------------------------------------------------
extern "C" void kernel_launch(void* const* d_in, const int* in_sizes, int n_in,
                              void* d_out, int out_size)
{
    (void)in_sizes; (void)n_in; (void)out_size;
    const float* edges = (const float*)d_in[0];
    const float* wq    = (const float*)d_in[1];
    const float* bq    = (const float*)d_in[2];
    const float* wk    = (const float*)d_in[3];
    const float* bk    = (const float*)d_in[4];
    const float* wv    = (const float*)d_in[5];
    const float* bv    = (const float*)d_in[6];
    const float* qcw   = (const float*)d_in[7];
    const float* qcb   = (const float*)d_in[8];
    const float* kcw   = (const float*)d_in[9];
    const float* kcb   = (const float*)d_in[10];
    const float* vcw   = (const float*)d_in[11];
    const float* vcb   = (const float*)d_in[12];
    const float* fcw   = (const float*)d_in[13];
    const float* fcb   = (const float*)d_in[14];
    const float* ln1g  = (const float*)d_in[15];
    const float* ln1b  = (const float*)d_in[16];
    const float* w1w   = (const float*)d_in[17];
    const float* w1b   = (const float*)d_in[18];
    const float* w2w   = (const float*)d_in[19];
    const float* w2b   = (const float*)d_in[20];
    const float* ln2g  = (const float*)d_in[21];
    const float* ln2b  = (const float*)d_in[22];

    static const int smem_qkv = 69120;
    static const int smem_fc  = 95744;
    static const int smem_mlp = 213504;
    cudaFuncSetAttribute(qkv_attn,  cudaFuncAttributeMaxDynamicSharedMemorySize, smem_qkv);
    cudaFuncSetAttribute(fc_tc,     cudaFuncAttributeMaxDynamicSharedMemorySize, smem_fc);
    cudaFuncSetAttribute(mlp_fused, cudaFuncAttributeMaxDynamicSharedMemorySize, smem_mlp);

    qkv_attn<<<dim3(64, 16), 384, smem_qkv>>>(edges, wq, bq, wk, bk, wv, bv,
                                              qcw, qcb, kcw, kcb, vcw, vcb);
    fc_tc<<<dim3(16, KSPLIT), 256, smem_fc>>>(fcw);
    mlp_fused<<<64, 256, smem_mlp>>>(edges, fcb, ln1g, ln1b,
                                     w1w, w1b, w2w, w2b, ln2g, ln2b,
                                     (float*)d_out);
}

// round 7
// speedup vs baseline: 1.6867x; 1.0683x over previous
#include <cuda_runtime.h>

// Problem constants
#define DM    100
#define NSDK  2048
#define ROWS  1024        // SZ_B * L
#define DI_   400
#define KSPLIT 8
#define PART_STRIDE (ROWS * DM)
#define LOG2E 1.44269504088896340736f

// Scratch (device globals — no allocation)
__device__ float g_att[ROWS * NSDK];          // attention output [1024][2048]
__device__ float g_part[KSPLIT * PART_STRIDE];// fc split-K partials

// ---------------------------------------------------------------------------
// helpers
// ---------------------------------------------------------------------------
__device__ __forceinline__ unsigned f2tf(float v) {
    unsigned r;
    asm("cvt.rna.tf32.f32 %0, %1;" : "=r"(r) : "f"(v));
    return r;
}

__device__ __forceinline__ void mma_tf32(float c[4],
                                         unsigned a0, unsigned a1, unsigned a2, unsigned a3,
                                         unsigned b0, unsigned b1) {
    asm("mma.sync.aligned.m16n8k8.row.col.f32.tf32.tf32.f32 "
        "{%0,%1,%2,%3},{%4,%5,%6,%7},{%8,%9},{%0,%1,%2,%3};"
        : "+f"(c[0]), "+f"(c[1]), "+f"(c[2]), "+f"(c[3])
        : "r"(a0), "r"(a1), "r"(a2), "r"(a3), "r"(b0), "r"(b1));
}

__device__ __forceinline__ unsigned sa(const void* p) {
    return (unsigned)__cvta_generic_to_shared(p);
}
__device__ __forceinline__ void cp16(unsigned d, const void* s) {
    asm volatile("cp.async.ca.shared.global [%0], [%1], 16;" :: "r"(d), "l"(s));
}
__device__ __forceinline__ void cp16z(unsigned d, const void* s, int srcbytes) {
    asm volatile("cp.async.ca.shared.global [%0], [%1], 16, %2;"
                 :: "r"(d), "l"(s), "r"(srcbytes));
}
#define CP_COMMIT    asm volatile("cp.async.commit_group;")
#define CP_WAIT_1    asm volatile("cp.async.wait_group 1;")
#define CP_WAIT_0    asm volatile("cp.async.wait_group 0;")
#define CP_WAIT_ALL  asm volatile("cp.async.wait_all;")

// ---------------------------------------------------------------------------
// K1: FUSED QKV projection + attention. K=100 fully smem-resident.
// Block 384 thr (12 warps): warp = proj (w>>2) x m-slice ((w&3)*16).
// Staging layout: [batch][flat64] pitch 68 -> immediate-offset LDS in softmax.
// grid (64 ns, 16 rowtiles). Dynamic smem 69120 B.
// ---------------------------------------------------------------------------
__global__ __launch_bounds__(384) void qkv_attn(
        const float* __restrict__ edges,
        const float* __restrict__ wq, const float* __restrict__ bq,
        const float* __restrict__ wk, const float* __restrict__ bk,
        const float* __restrict__ wv, const float* __restrict__ bv,
        const float* __restrict__ qcw, const float* __restrict__ qcb,
        const float* __restrict__ kcw, const float* __restrict__ kcb,
        const float* __restrict__ vcw, const float* __restrict__ vcb)
{
    extern __shared__ float smem[];
    float* A = smem;                 // [64][108]
    float* B = smem + 64 * 108;      // [96][108]
    // attention staging (union with A): [32 batches][68], per projection
    float* sq = smem;                // 2176 floats
    float* sk = smem + 2176;
    float* sv = smem + 4352;         // ends at 6528 <= 6912 (A region)

    const int t    = threadIdx.x;
    const int lane = t & 31;
    const int wid  = t >> 5;
    const int tig  = lane & 3;
    const int gid  = lane >> 2;

    const int ns   = blockIdx.x;
    const int row0 = blockIdx.y * 64;

    const int pw = wid >> 2;
    const int m0 = (wid & 3) * 16;

    for (int idx = t; idx < 1600; idx += 384) {
        int r = idx / 25, q = idx - r * 25;
        cp16(sa(A + r * 108 + q * 4), edges + (row0 + r) * DM + q * 4);
    }
    for (int idx = t; idx < 2400; idx += 384) {
        int rr = idx / 25, q = idx - rr * 25;
        int p = rr >> 5, n = rr & 31;
        const float* W = (p == 0) ? wq : (p == 1) ? wk : wv;
        cp16(sa(B + rr * 108 + q * 4), W + (ns * 32 + n) * DM + q * 4);
    }
    CP_COMMIT; CP_WAIT_ALL;
    for (int idx = t; idx < 160; idx += 384) {
        float* ptr = smem + idx * 108 + 100;
        ptr[0] = 0.0f; ptr[1] = 0.0f; ptr[2] = 0.0f; ptr[3] = 0.0f;
    }
    __syncthreads();

    float acc[4][4] = {};
    #pragma unroll
    for (int ks = 0; ks < 13; ks++) {
        const int k0 = ks * 8;
        unsigned a0 = f2tf(A[(m0 + gid) * 108 + k0 + tig]);
        unsigned a1 = f2tf(A[(m0 + gid + 8) * 108 + k0 + tig]);
        unsigned a2 = f2tf(A[(m0 + gid) * 108 + k0 + tig + 4]);
        unsigned a3 = f2tf(A[(m0 + gid + 8) * 108 + k0 + tig + 4]);
        #pragma unroll
        for (int j = 0; j < 4; j++) {
            const int brow = pw * 32 + j * 8 + gid;
            unsigned b0 = f2tf(B[brow * 108 + k0 + tig]);
            unsigned b1 = f2tf(B[brow * 108 + k0 + tig + 4]);
            mma_tf32(acc[j], a0, a1, a2, a3, b0, b1);
        }
    }

    __syncthreads();   // all mma smem reads done before union overwrite

    // epilogue: affine + bias -> staging [batch][l*32+dk] pitch 68
    {
        const float scale = (pw == 0) ? *qcw : (pw == 1) ? *kcw : *vcw;
        const float shift = (pw == 0) ? *qcb : (pw == 1) ? *kcb : *vcb;
        const float* bias = (pw == 0) ? bq : (pw == 1) ? bk : bv;
        float* sX = (pw == 0) ? sq : (pw == 1) ? sk : sv;

        #pragma unroll
        for (int j = 0; j < 4; j++) {
            const int col = j * 8 + 2 * tig;
            const float b0v = bias[ns * 32 + col];
            const float b1v = bias[ns * 32 + col + 1];
            #pragma unroll
            for (int i = 0; i < 2; i++) {
                const int r = m0 + gid + i * 8;         // local row 0..63
                const int off = (r >> 1) * 68 + (r & 1) * 32 + col;
                sX[off]     = fmaf(scale, acc[j][2 * i] + b0v, shift);
                sX[off + 1] = fmaf(scale, acc[j][2 * i + 1] + b1v, shift);
            }
        }
    }
    __syncthreads();

    // ---- attention: single-pass softmax, 2048 items = 32 batches x 64 ----
    for (int idx = t; idx < 2048; idx += 384) {
        const int bloc = idx >> 6;
        const int lt   = idx & 63;
        const int w    = lt & 1;
        const int h    = lt >> 1;
        const int base = bloc * 68;

        const float q = sq[base + lt] * LOG2E;   // pre-scaled for exp2
        const float* Kp = sk + base + w;         // K[2g] at immediate offsets
        const float* Vp = sv + base + w;

        // in-W terms (both l positions of own h)
        const int f0 = lt & ~1;                  // 2h
        const float ew0 = q * sk[base + f0];
        const float ew1 = q * sk[base + f0 + 1];
        float p0 = exp2f(ew0);
        float p1 = exp2f(ew1);
        float Z   = p0 + p1;
        float acc2 = p0 * sv[base + f0] + p1 * sv[base + f0 + 1];

        // cross-H terms, diag masked via exp2(-1e30)=0
        #pragma unroll
        for (int g = 0; g < 32; g++) {
            float e  = (g == h) ? -1e30f : q * Kp[2 * g];
            float pz = exp2f(e);
            Z   += pz;
            acc2 = fmaf(pz, Vp[2 * g], acc2);
        }

        const float o = acc2 / Z;
        const int grow = row0 + 2 * bloc + (lt >> 5);
        g_att[grow * NSDK + ns * 32 + (lt & 31)] = o;
    }
}

// ---------------------------------------------------------------------------
// K2: fc GEMM split-K (tf32), double-buffered cp.async, 256 threads (8 warps:
// 4M x 2N, warp tile 16x56). Tile 64(M) x 112(N), 4 chunks of K=64.
// grid (16, 8). Dynamic smem 95744 B.
// ---------------------------------------------------------------------------
__global__ __launch_bounds__(256) void fc_tc(const float* __restrict__ fcw)
{
    extern __shared__ float smem[];
    // buf b at offset b*11968: A[64][68] then B[112][68]

    const int t    = threadIdx.x;
    const int lane = t & 31;
    const int wid  = t >> 5;
    const int tig  = lane & 3;
    const int gid  = lane >> 2;

    const int row0 = blockIdx.x * 64;
    const int ks   = blockIdx.y;

    const int wm0 = (wid >> 1) * 16;
    const int wn0 = (wid & 1) * 56;

    float acc[7][4] = {};

    auto load_chunk = [&](int c, int buf) {
        const int kb = ks * 256 + c * 64;
        float* A = smem + buf * 11968;
        float* B = A + 4352;
        for (int idx = t; idx < 1024; idx += 256) {
            int r = idx >> 4, q = idx & 15;
            cp16(sa(A + r * 68 + q * 4), g_att + (row0 + r) * NSDK + kb + q * 4);
        }
        for (int idx = t; idx < 1792; idx += 256) {
            int r = idx >> 4, q = idx & 15;
            int rc = (r < DM) ? r : (DM - 1);
            cp16z(sa(B + r * 68 + q * 4), fcw + rc * NSDK + kb + q * 4,
                  (r < DM) ? 16 : 0);
        }
        CP_COMMIT;
    };

    load_chunk(0, 0);

    for (int c = 0; c < 4; c++) {
        if (c < 3) load_chunk(c + 1, (c + 1) & 1);
        if (c < 3) { CP_WAIT_1; } else { CP_WAIT_0; }
        __syncthreads();

        const float* A = smem + (c & 1) * 11968;
        const float* B = A + 4352;

        #pragma unroll
        for (int kss = 0; kss < 8; kss++) {
            const int k0 = kss * 8;
            unsigned a0 = f2tf(A[(wm0 + gid) * 68 + k0 + tig]);
            unsigned a1 = f2tf(A[(wm0 + gid + 8) * 68 + k0 + tig]);
            unsigned a2 = f2tf(A[(wm0 + gid) * 68 + k0 + tig + 4]);
            unsigned a3 = f2tf(A[(wm0 + gid + 8) * 68 + k0 + tig + 4]);
            #pragma unroll
            for (int j = 0; j < 7; j++) {
                const int brow = wn0 + j * 8 + gid;
                unsigned b0 = f2tf(B[brow * 68 + k0 + tig]);
                unsigned b1 = f2tf(B[brow * 68 + k0 + tig + 4]);
                mma_tf32(acc[j], a0, a1, a2, a3, b0, b1);
            }
        }
        __syncthreads();
    }

    #pragma unroll
    for (int j = 0; j < 7; j++) {
        const int col = wn0 + j * 8 + 2 * tig;
        if (col < DM) {
            int r0 = row0 + wm0 + gid;
            *(float2*)&g_part[ks * PART_STRIDE + r0 * DM + col] =
                make_float2(acc[j][0], acc[j][1]);
            *(float2*)&g_part[ks * PART_STRIDE + (r0 + 8) * DM + col] =
                make_float2(acc[j][2], acc[j][3]);
        }
    }
}

// ---------------------------------------------------------------------------
// K3: FUSED tail: partials-reduce + LN1 + MLP-l1(relu) + MLP-l2 + LN2 -> out.
// 16 rows/block, grid 64, 256 threads (8 warps). All intermediates in smem.
// ---------------------------------------------------------------------------
__global__ __launch_bounds__(256) void mlp_fused(
        const float* __restrict__ edges, const float* __restrict__ fcb,
        const float* __restrict__ ln1g,  const float* __restrict__ ln1b,
        const float* __restrict__ w1,    const float* __restrict__ w1b,
        const float* __restrict__ w2,    const float* __restrict__ w2b,
        const float* __restrict__ ln2g,  const float* __restrict__ ln2b,
        float* __restrict__ outp)
{
    extern __shared__ float smem[];
    float* xs  = smem;            // [16][108]  LN1 output (k-pad zeroed)
    float* hs  = smem + 1728;     // [16][420]  hidden (cols 400..415 zeroed)
    float* sR0 = smem + 8448;
    float* sR1 = smem + 30912;

    const int t    = threadIdx.x;
    const int lane = t & 31;
    const int wid  = t >> 5;
    const int tig  = lane & 3;
    const int gid  = lane >> 2;
    const int row0 = blockIdx.x * 16;

    auto cp_w1 = [&](int chunk, float* R) {
        const int rows = chunk ? 192 : 208;
        const int base = chunk * 208;
        for (int idx = t; idx < rows * 26; idx += 256) {
            int r = idx / 26, q = idx - r * 26;
            if (q < 25)
                cp16(sa(R + r * 108 + q * 4), w1 + (base + r) * DM + q * 4);
            else
                cp16z(sa(R + r * 108 + 100), w1, 0);
        }
        CP_COMMIT;
    };

    auto cp_w2 = [&](int chunk, float* R) {
        const int kbase = chunk * 208;
        for (int idx = t; idx < 104 * 52; idx += 256) {
            int r = idx / 52, q = idx - r * 52;
            int k = kbase + q * 4;
            int ok = (r < DM) && (k + 4 <= DI_);
            cp16z(sa(R + r * 212 + q * 4),
                  w2 + (ok ? r * DI_ + k : 0), ok ? 16 : 0);
        }
        CP_COMMIT;
    };

    cp_w1(0, sR0);                                   // G0

    for (int idx = t; idx < 1600; idx += 256) {
        int r = idx / 100, c = idx - r * 100;
        int grow = row0 + r;
        float v = fcb[c] + edges[grow * DM + c];
        #pragma unroll
        for (int s = 0; s < KSPLIT; s++)
            v += g_part[s * PART_STRIDE + grow * DM + c];
        xs[r * 108 + c] = v;
    }
    __syncthreads();

    if (t < 64) {
        const int r = t >> 2, s4 = t & 3;
        float vals[25];
        float sum = 0.0f;
        #pragma unroll
        for (int j = 0; j < 25; j++) {
            float v = xs[r * 108 + s4 + 4 * j];
            vals[j] = v;  sum += v;
        }
        sum += __shfl_xor_sync(0xffffffffu, sum, 1);
        sum += __shfl_xor_sync(0xffffffffu, sum, 2);
        const float mean = sum * (1.0f / DM);
        float v2 = 0.0f;
        #pragma unroll
        for (int j = 0; j < 25; j++) {
            float d = vals[j] - mean;
            v2 = fmaf(d, d, v2);
        }
        v2 += __shfl_xor_sync(0xffffffffu, v2, 1);
        v2 += __shfl_xor_sync(0xffffffffu, v2, 2);
        const float inv = rsqrtf(v2 * (1.0f / DM) + 1e-5f);
        #pragma unroll
        for (int j = 0; j < 25; j++) {
            int c = s4 + 4 * j;
            xs[r * 108 + c] = (vals[j] - mean) * inv * ln1g[c] + ln1b[c];
        }
        if (s4 == 0) {
            xs[r * 108 + 100] = 0.0f; xs[r * 108 + 101] = 0.0f;
            xs[r * 108 + 102] = 0.0f; xs[r * 108 + 103] = 0.0f;
        }
    }

    cp_w1(1, sR1);                                   // G1
    CP_WAIT_1; __syncthreads();                      // G0 done

    auto layer1_chunk = [&](int chunk, const float* R) {
        const int nfr = chunk ? 24 : 26;
        const int nmy = (nfr - wid + 7) >> 3;
        const int nbg = chunk * 208;
        float acc[4][4] = {};
        #pragma unroll
        for (int ks = 0; ks < 13; ks++) {
            const int k0 = ks * 8;
            unsigned a0 = f2tf(xs[gid * 108 + k0 + tig]);
            unsigned a1 = f2tf(xs[(gid + 8) * 108 + k0 + tig]);
            unsigned a2 = f2tf(xs[gid * 108 + k0 + tig + 4]);
            unsigned a3 = f2tf(xs[(gid + 8) * 108 + k0 + tig + 4]);
            #pragma unroll
            for (int j = 0; j < 4; j++) {
                if (j < nmy) {
                    int brow = (wid + 8 * j) * 8 + gid;
                    unsigned b0 = f2tf(R[brow * 108 + k0 + tig]);
                    unsigned b1 = f2tf(R[brow * 108 + k0 + tig + 4]);
                    mma_tf32(acc[j], a0, a1, a2, a3, b0, b1);
                }
            }
        }
        #pragma unroll
        for (int j = 0; j < 4; j++) {
            if (j < nmy) {
                int cg = nbg + (wid + 8 * j) * 8 + 2 * tig;
                float bb0 = w1b[cg], bb1 = w1b[cg + 1];
                hs[gid * 420 + cg]           = fmaxf(acc[j][0] + bb0, 0.0f);
                hs[gid * 420 + cg + 1]       = fmaxf(acc[j][1] + bb1, 0.0f);
                hs[(gid + 8) * 420 + cg]     = fmaxf(acc[j][2] + bb0, 0.0f);
                hs[(gid + 8) * 420 + cg + 1] = fmaxf(acc[j][3] + bb1, 0.0f);
            }
        }
    };

    layer1_chunk(0, sR0);
    __syncthreads();
    cp_w2(0, sR0);                                   // G2
    CP_WAIT_1; __syncthreads();                      // G1 done
    layer1_chunk(1, sR1);
    {
        int r = t >> 4, c = 400 + (t & 15);
        hs[r * 420 + c] = 0.0f;
    }
    __syncthreads();
    cp_w2(1, sR1);                                   // G3
    CP_WAIT_1; __syncthreads();                      // G2 done

    const int nmy2 = (wid < 5) ? 2 : 1;
    float l2acc[2][4] = {};
    auto layer2_chunk = [&](int chunk, const float* R) {
        #pragma unroll 2
        for (int ks = 0; ks < 26; ks++) {
            const int k0 = ks * 8;
            const int kk = chunk * 208 + k0;
            unsigned a0 = f2tf(hs[gid * 420 + kk + tig]);
            unsigned a1 = f2tf(hs[(gid + 8) * 420 + kk + tig]);
            unsigned a2 = f2tf(hs[gid * 420 + kk + tig + 4]);
            unsigned a3 = f2tf(hs[(gid + 8) * 420 + kk + tig + 4]);
            #pragma unroll
            for (int j = 0; j < 2; j++) {
                if (j < nmy2) {
                    int brow = (wid + 8 * j) * 8 + gid;
                    unsigned b0 = f2tf(R[brow * 212 + k0 + tig]);
                    unsigned b1 = f2tf(R[brow * 212 + k0 + tig + 4]);
                    mma_tf32(l2acc[j], a0, a1, a2, a3, b0, b1);
                }
            }
        }
    };

    layer2_chunk(0, sR0);
    CP_WAIT_0; __syncthreads();                      // G3 done
    layer2_chunk(1, sR1);

    __syncthreads();
    float* ys = sR0;                                 // [16][104]
    #pragma unroll
    for (int j = 0; j < 2; j++) {
        if (j < nmy2) {
            int col = (wid + 8 * j) * 8 + 2 * tig;
            ys[gid * 104 + col]           = l2acc[j][0];
            ys[gid * 104 + col + 1]       = l2acc[j][1];
            ys[(gid + 8) * 104 + col]     = l2acc[j][2];
            ys[(gid + 8) * 104 + col + 1] = l2acc[j][3];
        }
    }
    __syncthreads();

    if (t < 64) {
        const int r    = t >> 2;
        const int s4   = t & 3;
        const int grow = row0 + r;

        float vals[25];
        float sum = 0.0f;
        #pragma unroll
        for (int j = 0; j < 25; j++) {
            int c = s4 + 4 * j;
            float v = ys[r * 104 + c] + w2b[c] + xs[r * 108 + c];
            vals[j] = v;  sum += v;
        }
        sum += __shfl_xor_sync(0xffffffffu, sum, 1);
        sum += __shfl_xor_sync(0xffffffffu, sum, 2);
        const float mean = sum * (1.0f / DM);

        float v2 = 0.0f;
        #pragma unroll
        for (int j = 0; j < 25; j++) {
            float d = vals[j] - mean;
            v2 = fmaf(d, d, v2);
        }
        v2 += __shfl_xor_sync(0xffffffffu, v2, 1);
        v2 += __shfl_xor_sync(0xffffffffu, v2, 2);
        const float inv = rsqrtf(v2 * (1.0f / DM) + 1e-5f);

        #pragma unroll
        for (int j = 0; j < 25; j++) {
            int c = s4 + 4 * j;
            outp[grow * DM + c] = (vals[j] - mean) * inv * ln2g[c] + ln2b[c];
        }
    }
}

// ---------------------------------------------------------------------------
extern "C" void kernel_launch(void* const* d_in, const int* in_sizes, int n_in,
                              void* d_out, int out_size)
{
    (void)in_sizes; (void)n_in; (void)out_size;
    const float* edges = (const float*)d_in[0];
    const float* wq    = (const float*)d_in[1];
    const float* bq    = (const float*)d_in[2];
    const float* wk    = (const float*)d_in[3];
    const float* bk    = (const float*)d_in[4];
    const float* wv    = (const float*)d_in[5];
    const float* bv    = (const float*)d_in[6];
    const float* qcw   = (const float*)d_in[7];
    const float* qcb   = (const float*)d_in[8];
    const float* kcw   = (const float*)d_in[9];
    const float* kcb   = (const float*)d_in[10];
    const float* vcw   = (const float*)d_in[11];
    const float* vcb   = (const float*)d_in[12];
    const float* fcw   = (const float*)d_in[13];
    const float* fcb   = (const float*)d_in[14];
    const float* ln1g  = (const float*)d_in[15];
    const float* ln1b  = (const float*)d_in[16];
    const float* w1w   = (const float*)d_in[17];
    const float* w1b   = (const float*)d_in[18];
    const float* w2w   = (const float*)d_in[19];
    const float* w2b   = (const float*)d_in[20];
    const float* ln2g  = (const float*)d_in[21];
    const float* ln2b  = (const float*)d_in[22];

    static const int smem_qkv = 69120;
    static const int smem_fc  = 95744;
    static const int smem_mlp = 213504;
    cudaFuncSetAttribute(qkv_attn,  cudaFuncAttributeMaxDynamicSharedMemorySize, smem_qkv);
    cudaFuncSetAttribute(fc_tc,     cudaFuncAttributeMaxDynamicSharedMemorySize, smem_fc);
    cudaFuncSetAttribute(mlp_fused, cudaFuncAttributeMaxDynamicSharedMemorySize, smem_mlp);

    qkv_attn<<<dim3(64, 16), 384, smem_qkv>>>(edges, wq, bq, wk, bk, wv, bv,
                                              qcw, qcb, kcw, kcb, vcw, vcb);
    fc_tc<<<dim3(16, KSPLIT), 256, smem_fc>>>(fcw);
    mlp_fused<<<64, 256, smem_mlp>>>(edges, fcb, ln1g, ln1b,
                                     w1w, w1b, w2w, w2b, ln2g, ln2b,
                                     (float*)d_out);
}

// round 8
// speedup vs baseline: 1.7804x; 1.0556x over previous
#include <cuda_runtime.h>

// Problem constants
#define DM    100
#define NSDK  2048
#define ROWS  1024        // SZ_B * L
#define DI_   400
#define KSPLIT 8
#define PART_STRIDE (ROWS * DM)
#define LOG2E 1.44269504088896340736f

// Scratch (device globals — no allocation)
__device__ float g_att[ROWS * NSDK];          // attention output [1024][2048]
__device__ float g_part[KSPLIT * PART_STRIDE];// fc split-K partials

// ---------------------------------------------------------------------------
// helpers
// ---------------------------------------------------------------------------
__device__ __forceinline__ unsigned f2tf(float v) {
    unsigned r;
    asm("cvt.rna.tf32.f32 %0, %1;" : "=r"(r) : "f"(v));
    return r;
}

__device__ __forceinline__ void cvt4_inplace(float* p) {
    float4 v = *(float4*)p;
    unsigned u0 = f2tf(v.x), u1 = f2tf(v.y), u2 = f2tf(v.z), u3 = f2tf(v.w);
    uint4 w = make_uint4(u0, u1, u2, u3);
    *(uint4*)p = w;
}

__device__ __forceinline__ void mma_tf32(float c[4],
                                         unsigned a0, unsigned a1, unsigned a2, unsigned a3,
                                         unsigned b0, unsigned b1) {
    asm("mma.sync.aligned.m16n8k8.row.col.f32.tf32.tf32.f32 "
        "{%0,%1,%2,%3},{%4,%5,%6,%7},{%8,%9},{%0,%1,%2,%3};"
        : "+f"(c[0]), "+f"(c[1]), "+f"(c[2]), "+f"(c[3])
        : "r"(a0), "r"(a1), "r"(a2), "r"(a3), "r"(b0), "r"(b1));
}

__device__ __forceinline__ unsigned sa(const void* p) {
    return (unsigned)__cvta_generic_to_shared(p);
}
__device__ __forceinline__ void cp16(unsigned d, const void* s) {
    asm volatile("cp.async.ca.shared.global [%0], [%1], 16;" :: "r"(d), "l"(s));
}
__device__ __forceinline__ void cp16z(unsigned d, const void* s, int srcbytes) {
    asm volatile("cp.async.ca.shared.global [%0], [%1], 16, %2;"
                 :: "r"(d), "l"(s), "r"(srcbytes));
}
#define CP_COMMIT    asm volatile("cp.async.commit_group;")
#define CP_WAIT_1    asm volatile("cp.async.wait_group 1;")
#define CP_WAIT_0    asm volatile("cp.async.wait_group 0;")
#define CP_WAIT_ALL  asm volatile("cp.async.wait_all;")

// ---------------------------------------------------------------------------
// K1: FUSED QKV projection + attention. K=100 smem-resident, tf32 converted
// in place once. Attention staging de-interleaved [batch][w][h] (pitch 68)
// -> float4 broadcast loads + branch-free diag correction.
// Block 384 thr (12 warps): warp = proj (w>>2) x m-slice ((w&3)*16).
// grid (64 ns, 16 rowtiles). Dynamic smem 69120 B.
// ---------------------------------------------------------------------------
__global__ __launch_bounds__(384) void qkv_attn(
        const float* __restrict__ edges,
        const float* __restrict__ wq, const float* __restrict__ bq,
        const float* __restrict__ wk, const float* __restrict__ bk,
        const float* __restrict__ wv, const float* __restrict__ bv,
        const float* __restrict__ qcw, const float* __restrict__ qcb,
        const float* __restrict__ kcw, const float* __restrict__ kcb,
        const float* __restrict__ vcw, const float* __restrict__ vcb)
{
    extern __shared__ float smem[];
    float* A = smem;                 // [64][108]
    float* B = smem + 64 * 108;      // [96][108]
    // attention staging (union with A): [32 batches][2 w][32 h], pitch 68
    float* sq = smem;                // 2176 floats
    float* sk = smem + 2176;
    float* sv = smem + 4352;         // ends at 6528 <= 6912 (A region)

    const int t    = threadIdx.x;
    const int lane = t & 31;
    const int wid  = t >> 5;
    const int tig  = lane & 3;
    const int gid  = lane >> 2;

    const int ns   = blockIdx.x;
    const int row0 = blockIdx.y * 64;

    const int pw = wid >> 2;
    const int m0 = (wid & 3) * 16;

    for (int idx = t; idx < 1600; idx += 384) {
        int r = idx / 25, q = idx - r * 25;
        cp16(sa(A + r * 108 + q * 4), edges + (row0 + r) * DM + q * 4);
    }
    for (int idx = t; idx < 2400; idx += 384) {
        int rr = idx / 25, q = idx - rr * 25;
        int p = rr >> 5, n = rr & 31;
        const float* W = (p == 0) ? wq : (p == 1) ? wk : wv;
        cp16(sa(B + rr * 108 + q * 4), W + (ns * 32 + n) * DM + q * 4);
    }
    CP_COMMIT; CP_WAIT_ALL;

    // convert own-loaded data f32 -> tf32 in place (same idx mapping as cp),
    // and zero the k-pad (cols 100..103). No barrier needed before this.
    for (int idx = t; idx < 1600; idx += 384) {
        int r = idx / 25, q = idx - r * 25;
        cvt4_inplace(A + r * 108 + q * 4);
    }
    for (int idx = t; idx < 2400; idx += 384) {
        int rr = idx / 25, q = idx - rr * 25;
        cvt4_inplace(B + rr * 108 + q * 4);
    }
    for (int idx = t; idx < 160; idx += 384) {
        float* ptr = smem + idx * 108 + 100;
        ptr[0] = 0.0f; ptr[1] = 0.0f; ptr[2] = 0.0f; ptr[3] = 0.0f;
    }
    __syncthreads();

    const unsigned* Au = (const unsigned*)A;
    const unsigned* Bu = (const unsigned*)B;

    float acc[4][4] = {};
    #pragma unroll
    for (int ks = 0; ks < 13; ks++) {
        const int k0 = ks * 8;
        unsigned a0 = Au[(m0 + gid) * 108 + k0 + tig];
        unsigned a1 = Au[(m0 + gid + 8) * 108 + k0 + tig];
        unsigned a2 = Au[(m0 + gid) * 108 + k0 + tig + 4];
        unsigned a3 = Au[(m0 + gid + 8) * 108 + k0 + tig + 4];
        #pragma unroll
        for (int j = 0; j < 4; j++) {
            const int brow = pw * 32 + j * 8 + gid;
            unsigned b0 = Bu[brow * 108 + k0 + tig];
            unsigned b1 = Bu[brow * 108 + k0 + tig + 4];
            mma_tf32(acc[j], a0, a1, a2, a3, b0, b1);
        }
    }

    __syncthreads();   // all mma smem reads done before union overwrite

    // epilogue: affine + bias -> staging [batch][w*32 + h], pitch 68
    // (h = 16*l + dk/2, w = dk&1 for element (l, dk))
    {
        const float scale = (pw == 0) ? *qcw : (pw == 1) ? *kcw : *vcw;
        const float shift = (pw == 0) ? *qcb : (pw == 1) ? *kcb : *vcb;
        const float* bias = (pw == 0) ? bq : (pw == 1) ? bk : bv;
        float* sX = (pw == 0) ? sq : (pw == 1) ? sk : sv;

        #pragma unroll
        for (int j = 0; j < 4; j++) {
            const int col = j * 8 + 2 * tig;           // even
            const float b0v = bias[ns * 32 + col];
            const float b1v = bias[ns * 32 + col + 1];
            #pragma unroll
            for (int i = 0; i < 2; i++) {
                const int r = m0 + gid + i * 8;        // local row 0..63
                const int off = (r >> 1) * 68 + (r & 1) * 16 + (col >> 1);
                sX[off]      = fmaf(scale, acc[j][2 * i] + b0v, shift);
                sX[off + 32] = fmaf(scale, acc[j][2 * i + 1] + b1v, shift);
            }
        }
    }
    __syncthreads();

    // ---- attention: branch-free softmax, 2048 items = 32 batches x 64 ----
    for (int idx = t; idx < 2048; idx += 384) {
        const int bloc   = idx >> 6;
        const int within = idx & 63;         // = w*32 + h
        const int w      = within >> 5;
        const int h      = within & 31;
        const int base   = bloc * 68;

        const float q = sq[base + within] * LOG2E;
        const float* Kw = sk + base + w * 32;    // K[·, w], h-contiguous
        const float* Vw = sv + base + w * 32;

        float Z = 0.0f, acc2 = 0.0f;
        #pragma unroll
        for (int c = 0; c < 8; c++) {
            float4 k4 = *(const float4*)(Kw + 4 * c);   // warp-broadcast
            float4 v4 = *(const float4*)(Vw + 4 * c);
            float p;
            p = exp2f(q * k4.x); Z += p; acc2 = fmaf(p, v4.x, acc2);
            p = exp2f(q * k4.y); Z += p; acc2 = fmaf(p, v4.y, acc2);
            p = exp2f(q * k4.z); Z += p; acc2 = fmaf(p, v4.z, acc2);
            p = exp2f(q * k4.w); Z += p; acc2 = fmaf(p, v4.w, acc2);
        }

        // in-W terms + diag removal. Cross loop included g==h with value
        // pd = exp2(q*K[h,w]) which equals the in-W v==w term.
        const float k0v = sk[base + h];        // K[h,0]
        const float k1v = sk[base + 32 + h];   // K[h,1]
        const float v0v = sv[base + h];
        const float v1v = sv[base + 32 + h];
        const float p0 = exp2f(q * k0v);
        const float p1 = exp2f(q * k1v);
        const float pd = w ? p1 : p0;
        const float vd = w ? v1v : v0v;

        Z    = Z - pd + p0 + p1;
        acc2 = acc2 - pd * vd + p0 * v0v + p1 * v1v;

        const float o = __fdividef(acc2, Z);
        const int l   = h >> 4;
        const int dk  = 2 * (h & 15) + w;
        const int grow = row0 + 2 * bloc + l;
        g_att[grow * NSDK + ns * 32 + dk] = o;
    }
}

// ---------------------------------------------------------------------------
// K2: fc GEMM split-K (tf32), double-buffered cp.async, in-place tf32 cvt.
// 256 threads (8 warps: 4M x 2N). Tile 64(M) x 112(N), 4 chunks of K=64.
// grid (16, 8). Dynamic smem 95744 B.
// ---------------------------------------------------------------------------
__global__ __launch_bounds__(256) void fc_tc(const float* __restrict__ fcw)
{
    extern __shared__ float smem[];
    // buf b at offset b*11968: A[64][68] then B[112][68]

    const int t    = threadIdx.x;
    const int lane = t & 31;
    const int wid  = t >> 5;
    const int tig  = lane & 3;
    const int gid  = lane >> 2;

    const int row0 = blockIdx.x * 64;
    const int ks   = blockIdx.y;

    const int wm0 = (wid >> 1) * 16;
    const int wn0 = (wid & 1) * 56;

    float acc[7][4] = {};

    auto load_chunk = [&](int c, int buf) {
        const int kb = ks * 256 + c * 64;
        float* A = smem + buf * 11968;
        float* B = A + 4352;
        for (int idx = t; idx < 1024; idx += 256) {
            int r = idx >> 4, q = idx & 15;
            cp16(sa(A + r * 68 + q * 4), g_att + (row0 + r) * NSDK + kb + q * 4);
        }
        for (int idx = t; idx < 1792; idx += 256) {
            int r = idx >> 4, q = idx & 15;
            int rc = (r < DM) ? r : (DM - 1);
            cp16z(sa(B + r * 68 + q * 4), fcw + rc * NSDK + kb + q * 4,
                  (r < DM) ? 16 : 0);
        }
        CP_COMMIT;
    };

    load_chunk(0, 0);

    for (int c = 0; c < 4; c++) {
        if (c < 3) load_chunk(c + 1, (c + 1) & 1);
        if (c < 3) { CP_WAIT_1; } else { CP_WAIT_0; }

        float* Af = smem + (c & 1) * 11968;
        float* Bf = Af + 4352;

        // convert own-loaded data in place (same mapping as load_chunk)
        for (int idx = t; idx < 1024; idx += 256) {
            int r = idx >> 4, q = idx & 15;
            cvt4_inplace(Af + r * 68 + q * 4);
        }
        for (int idx = t; idx < 1792; idx += 256) {
            int r = idx >> 4, q = idx & 15;
            cvt4_inplace(Bf + r * 68 + q * 4);
        }
        __syncthreads();

        const unsigned* A = (const unsigned*)Af;
        const unsigned* B = (const unsigned*)Bf;

        #pragma unroll
        for (int kss = 0; kss < 8; kss++) {
            const int k0 = kss * 8;
            unsigned a0 = A[(wm0 + gid) * 68 + k0 + tig];
            unsigned a1 = A[(wm0 + gid + 8) * 68 + k0 + tig];
            unsigned a2 = A[(wm0 + gid) * 68 + k0 + tig + 4];
            unsigned a3 = A[(wm0 + gid + 8) * 68 + k0 + tig + 4];
            #pragma unroll
            for (int j = 0; j < 7; j++) {
                const int brow = wn0 + j * 8 + gid;
                unsigned b0 = B[brow * 68 + k0 + tig];
                unsigned b1 = B[brow * 68 + k0 + tig + 4];
                mma_tf32(acc[j], a0, a1, a2, a3, b0, b1);
            }
        }
        __syncthreads();
    }

    #pragma unroll
    for (int j = 0; j < 7; j++) {
        const int col = wn0 + j * 8 + 2 * tig;
        if (col < DM) {
            int r0 = row0 + wm0 + gid;
            *(float2*)&g_part[ks * PART_STRIDE + r0 * DM + col] =
                make_float2(acc[j][0], acc[j][1]);
            *(float2*)&g_part[ks * PART_STRIDE + (r0 + 8) * DM + col] =
                make_float2(acc[j][2], acc[j][3]);
        }
    }
}

// ---------------------------------------------------------------------------
// K3: FUSED tail: partials-reduce + LN1 + MLP-l1(relu) + MLP-l2 + LN2 -> out.
// 16 rows/block, grid 64, 256 threads (8 warps). All intermediates in smem.
// ---------------------------------------------------------------------------
__global__ __launch_bounds__(256) void mlp_fused(
        const float* __restrict__ edges, const float* __restrict__ fcb,
        const float* __restrict__ ln1g,  const float* __restrict__ ln1b,
        const float* __restrict__ w1,    const float* __restrict__ w1b,
        const float* __restrict__ w2,    const float* __restrict__ w2b,
        const float* __restrict__ ln2g,  const float* __restrict__ ln2b,
        float* __restrict__ outp)
{
    extern __shared__ float smem[];
    float* xs  = smem;            // [16][108]  LN1 output (k-pad zeroed)
    float* hs  = smem + 1728;     // [16][420]  hidden (cols 400..415 zeroed)
    float* sR0 = smem + 8448;
    float* sR1 = smem + 30912;

    const int t    = threadIdx.x;
    const int lane = t & 31;
    const int wid  = t >> 5;
    const int tig  = lane & 3;
    const int gid  = lane >> 2;
    const int row0 = blockIdx.x * 16;

    auto cp_w1 = [&](int chunk, float* R) {
        const int rows = chunk ? 192 : 208;
        const int base = chunk * 208;
        for (int idx = t; idx < rows * 26; idx += 256) {
            int r = idx / 26, q = idx - r * 26;
            if (q < 25)
                cp16(sa(R + r * 108 + q * 4), w1 + (base + r) * DM + q * 4);
            else
                cp16z(sa(R + r * 108 + 100), w1, 0);
        }
        CP_COMMIT;
    };

    auto cp_w2 = [&](int chunk, float* R) {
        const int kbase = chunk * 208;
        for (int idx = t; idx < 104 * 52; idx += 256) {
            int r = idx / 52, q = idx - r * 52;
            int k = kbase + q * 4;
            int ok = (r < DM) && (k + 4 <= DI_);
            cp16z(sa(R + r * 212 + q * 4),
                  w2 + (ok ? r * DI_ + k : 0), ok ? 16 : 0);
        }
        CP_COMMIT;
    };

    cp_w1(0, sR0);                                   // G0

    for (int idx = t; idx < 1600; idx += 256) {
        int r = idx / 100, c = idx - r * 100;
        int grow = row0 + r;
        float v = fcb[c] + edges[grow * DM + c];
        #pragma unroll
        for (int s = 0; s < KSPLIT; s++)
            v += g_part[s * PART_STRIDE + grow * DM + c];
        xs[r * 108 + c] = v;
    }
    __syncthreads();

    if (t < 64) {
        const int r = t >> 2, s4 = t & 3;
        float vals[25];
        float sum = 0.0f;
        #pragma unroll
        for (int j = 0; j < 25; j++) {
            float v = xs[r * 108 + s4 + 4 * j];
            vals[j] = v;  sum += v;
        }
        sum += __shfl_xor_sync(0xffffffffu, sum, 1);
        sum += __shfl_xor_sync(0xffffffffu, sum, 2);
        const float mean = sum * (1.0f / DM);
        float v2 = 0.0f;
        #pragma unroll
        for (int j = 0; j < 25; j++) {
            float d = vals[j] - mean;
            v2 = fmaf(d, d, v2);
        }
        v2 += __shfl_xor_sync(0xffffffffu, v2, 1);
        v2 += __shfl_xor_sync(0xffffffffu, v2, 2);
        const float inv = rsqrtf(v2 * (1.0f / DM) + 1e-5f);
        #pragma unroll
        for (int j = 0; j < 25; j++) {
            int c = s4 + 4 * j;
            xs[r * 108 + c] = (vals[j] - mean) * inv * ln1g[c] + ln1b[c];
        }
        if (s4 == 0) {
            xs[r * 108 + 100] = 0.0f; xs[r * 108 + 101] = 0.0f;
            xs[r * 108 + 102] = 0.0f; xs[r * 108 + 103] = 0.0f;
        }
    }

    cp_w1(1, sR1);                                   // G1
    CP_WAIT_1; __syncthreads();                      // G0 done

    auto layer1_chunk = [&](int chunk, const float* R) {
        const int nfr = chunk ? 24 : 26;
        const int nmy = (nfr - wid + 7) >> 3;
        const int nbg = chunk * 208;
        float acc[4][4] = {};
        #pragma unroll
        for (int ks = 0; ks < 13; ks++) {
            const int k0 = ks * 8;
            unsigned a0 = f2tf(xs[gid * 108 + k0 + tig]);
            unsigned a1 = f2tf(xs[(gid + 8) * 108 + k0 + tig]);
            unsigned a2 = f2tf(xs[gid * 108 + k0 + tig + 4]);
            unsigned a3 = f2tf(xs[(gid + 8) * 108 + k0 + tig + 4]);
            #pragma unroll
            for (int j = 0; j < 4; j++) {
                if (j < nmy) {
                    int brow = (wid + 8 * j) * 8 + gid;
                    unsigned b0 = f2tf(R[brow * 108 + k0 + tig]);
                    unsigned b1 = f2tf(R[brow * 108 + k0 + tig + 4]);
                    mma_tf32(acc[j], a0, a1, a2, a3, b0, b1);
                }
            }
        }
        #pragma unroll
        for (int j = 0; j < 4; j++) {
            if (j < nmy) {
                int cg = nbg + (wid + 8 * j) * 8 + 2 * tig;
                float bb0 = w1b[cg], bb1 = w1b[cg + 1];
                hs[gid * 420 + cg]           = fmaxf(acc[j][0] + bb0, 0.0f);
                hs[gid * 420 + cg + 1]       = fmaxf(acc[j][1] + bb1, 0.0f);
                hs[(gid + 8) * 420 + cg]     = fmaxf(acc[j][2] + bb0, 0.0f);
                hs[(gid + 8) * 420 + cg + 1] = fmaxf(acc[j][3] + bb1, 0.0f);
            }
        }
    };

    layer1_chunk(0, sR0);
    __syncthreads();
    cp_w2(0, sR0);                                   // G2
    CP_WAIT_1; __syncthreads();                      // G1 done
    layer1_chunk(1, sR1);
    {
        int r = t >> 4, c = 400 + (t & 15);
        hs[r * 420 + c] = 0.0f;
    }
    __syncthreads();
    cp_w2(1, sR1);                                   // G3
    CP_WAIT_1; __syncthreads();                      // G2 done

    const int nmy2 = (wid < 5) ? 2 : 1;
    float l2acc[2][4] = {};
    auto layer2_chunk = [&](int chunk, const float* R) {
        #pragma unroll 2
        for (int ks = 0; ks < 26; ks++) {
            const int k0 = ks * 8;
            const int kk = chunk * 208 + k0;
            unsigned a0 = f2tf(hs[gid * 420 + kk + tig]);
            unsigned a1 = f2tf(hs[(gid + 8) * 420 + kk + tig]);
            unsigned a2 = f2tf(hs[gid * 420 + kk + tig + 4]);
            unsigned a3 = f2tf(hs[(gid + 8) * 420 + kk + tig + 4]);
            #pragma unroll
            for (int j = 0; j < 2; j++) {
                if (j < nmy2) {
                    int brow = (wid + 8 * j) * 8 + gid;
                    unsigned b0 = f2tf(R[brow * 212 + k0 + tig]);
                    unsigned b1 = f2tf(R[brow * 212 + k0 + tig + 4]);
                    mma_tf32(l2acc[j], a0, a1, a2, a3, b0, b1);
                }
            }
        }
    };

    layer2_chunk(0, sR0);
    CP_WAIT_0; __syncthreads();                      // G3 done
    layer2_chunk(1, sR1);

    __syncthreads();
    float* ys = sR0;                                 // [16][104]
    #pragma unroll
    for (int j = 0; j < 2; j++) {
        if (j < nmy2) {
            int col = (wid + 8 * j) * 8 + 2 * tig;
            ys[gid * 104 + col]           = l2acc[j][0];
            ys[gid * 104 + col + 1]       = l2acc[j][1];
            ys[(gid + 8) * 104 + col]     = l2acc[j][2];
            ys[(gid + 8) * 104 + col + 1] = l2acc[j][3];
        }
    }
    __syncthreads();

    if (t < 64) {
        const int r    = t >> 2;
        const int s4   = t & 3;
        const int grow = row0 + r;

        float vals[25];
        float sum = 0.0f;
        #pragma unroll
        for (int j = 0; j < 25; j++) {
            int c = s4 + 4 * j;
            float v = ys[r * 104 + c] + w2b[c] + xs[r * 108 + c];
            vals[j] = v;  sum += v;
        }
        sum += __shfl_xor_sync(0xffffffffu, sum, 1);
        sum += __shfl_xor_sync(0xffffffffu, sum, 2);
        const float mean = sum * (1.0f / DM);

        float v2 = 0.0f;
        #pragma unroll
        for (int j = 0; j < 25; j++) {
            float d = vals[j] - mean;
            v2 = fmaf(d, d, v2);
        }
        v2 += __shfl_xor_sync(0xffffffffu, v2, 1);
        v2 += __shfl_xor_sync(0xffffffffu, v2, 2);
        const float inv = rsqrtf(v2 * (1.0f / DM) + 1e-5f);

        #pragma unroll
        for (int j = 0; j < 25; j++) {
            int c = s4 + 4 * j;
            outp[grow * DM + c] = (vals[j] - mean) * inv * ln2g[c] + ln2b[c];
        }
    }
}

// ---------------------------------------------------------------------------
extern "C" void kernel_launch(void* const* d_in, const int* in_sizes, int n_in,
                              void* d_out, int out_size)
{
    (void)in_sizes; (void)n_in; (void)out_size;
    const float* edges = (const float*)d_in[0];
    const float* wq    = (const float*)d_in[1];
    const float* bq    = (const float*)d_in[2];
    const float* wk    = (const float*)d_in[3];
    const float* bk    = (const float*)d_in[4];
    const float* wv    = (const float*)d_in[5];
    const float* bv    = (const float*)d_in[6];
    const float* qcw   = (const float*)d_in[7];
    const float* qcb   = (const float*)d_in[8];
    const float* kcw   = (const float*)d_in[9];
    const float* kcb   = (const float*)d_in[10];
    const float* vcw   = (const float*)d_in[11];
    const float* vcb   = (const float*)d_in[12];
    const float* fcw   = (const float*)d_in[13];
    const float* fcb   = (const float*)d_in[14];
    const float* ln1g  = (const float*)d_in[15];
    const float* ln1b  = (const float*)d_in[16];
    const float* w1w   = (const float*)d_in[17];
    const float* w1b   = (const float*)d_in[18];
    const float* w2w   = (const float*)d_in[19];
    const float* w2b   = (const float*)d_in[20];
    const float* ln2g  = (const float*)d_in[21];
    const float* ln2b  = (const float*)d_in[22];

    static const int smem_qkv = 69120;
    static const int smem_fc  = 95744;
    static const int smem_mlp = 213504;
    cudaFuncSetAttribute(qkv_attn,  cudaFuncAttributeMaxDynamicSharedMemorySize, smem_qkv);
    cudaFuncSetAttribute(fc_tc,     cudaFuncAttributeMaxDynamicSharedMemorySize, smem_fc);
    cudaFuncSetAttribute(mlp_fused, cudaFuncAttributeMaxDynamicSharedMemorySize, smem_mlp);

    qkv_attn<<<dim3(64, 16), 384, smem_qkv>>>(edges, wq, bq, wk, bk, wv, bv,
                                              qcw, qcb, kcw, kcb, vcw, vcb);
    fc_tc<<<dim3(16, KSPLIT), 256, smem_fc>>>(fcw);
    mlp_fused<<<64, 256, smem_mlp>>>(edges, fcb, ln1g, ln1b,
                                     w1w, w1b, w2w, w2b, ln2g, ln2b,
                                     (float*)d_out);
}